// round 14
// baseline (speedup 1.0000x reference)
#include <cuda_runtime.h>
#include <cuda_bf16.h>
#include <cstdint>
#include <math.h>

#define NBATCH  512
#define T       1042
#define TP      1056
#define KE      6400
#define KT      528
#define M_EMB   8192
#define M_PAIR  65536
#define M_REL   4096

// ---------------- scratch (device globals; no allocation) ----------------
__device__ __align__(16) float g_P[(size_t)M_EMB * TP];
__device__ __align__(16) float g_Q[(size_t)M_EMB * TP];
__device__ __align__(16) float g_rel[(size_t)M_REL * TP];
__device__ __align__(16) float g_fo[M_REL];
__device__ __align__(16) float g_H1f[(size_t)M_PAIR * TP];
__device__ __align__(16) float g_H2f[(size_t)M_PAIR * TP];
// split (bf16 hi/lo, fragment-permuted) buffers
__device__ __align__(16) uint32_t g_xSp[(size_t)64 * 400 * 2048];
__device__ __align__(16) uint32_t g_taggedSp[(size_t)64 * 33 * 2048];
__device__ __align__(16) uint32_t g_H1Sp[(size_t)512 * 66 * 2048];
__device__ __align__(16) uint32_t g_H2Sp[(size_t)512 * 66 * 2048];
__device__ __align__(16) uint32_t g_WembSp[(size_t)4 * 400 * 2048];
__device__ __align__(16) uint32_t g_W1tSp[(size_t)9 * 33 * 2048];
__device__ __align__(16) uint32_t g_W1bSp[(size_t)9 * 33 * 2048];
__device__ __align__(16) uint32_t g_W2Sp[(size_t)7 * 66 * 2048];   // 160-tiling
__device__ __align__(16) uint32_t g_W3Sp[(size_t)7 * 66 * 2048];   // 160-tiling
__device__ __align__(16) uint32_t g_Wf1Sp[(size_t)9 * 66 * 2048];
__device__ __align__(16) float g_W2f[(size_t)TP * TP];
__device__ __align__(16) float g_W3f[(size_t)TP * TP];
__device__ __align__(16) float g_Wf2p[TP];
__device__ __align__(16) float g_b1[TP];
__device__ __align__(16) float g_b2[TP];
__device__ __align__(16) float g_b3[TP];
__device__ __align__(16) float g_bf1[TP];

// ---------------- helpers -------------------------------------------------
__device__ __forceinline__ void split2(float a, float b, uint32_t& h, uint32_t& l) {
    __nv_bfloat16 ha = __float2bfloat16(a);
    __nv_bfloat16 hb = __float2bfloat16(b);
    float fa = __bfloat162float(ha), fb = __bfloat162float(hb);
    __nv_bfloat16 la = __float2bfloat16(a - fa);
    __nv_bfloat16 lb = __float2bfloat16(b - fb);
    h = (uint32_t)__bfloat16_as_ushort(ha) | ((uint32_t)__bfloat16_as_ushort(hb) << 16);
    l = (uint32_t)__bfloat16_as_ushort(la) | ((uint32_t)__bfloat16_as_ushort(lb) << 16);
}

__device__ __forceinline__ void mma16(float acc[4], const uint32_t a[4], const uint32_t b[2]) {
    asm volatile(
        "mma.sync.aligned.m16n8k16.row.col.f32.bf16.bf16.f32 "
        "{%0,%1,%2,%3},{%4,%5,%6,%7},{%8,%9},{%0,%1,%2,%3};"
        : "+f"(acc[0]), "+f"(acc[1]), "+f"(acc[2]), "+f"(acc[3])
        : "r"(a[0]), "r"(a[1]), "r"(a[2]), "r"(a[3]), "r"(b[0]), "r"(b[1]));
}

__device__ __forceinline__ uint32_t smem_u32(const void* p) {
    uint32_t a;
    asm("{ .reg .u64 t; cvta.to.shared.u64 t, %1; cvt.u32.u64 %0, t; }" : "=r"(a) : "l"(p));
    return a;
}
#define CP16(saddr, gptr) \
    asm volatile("cp.async.cg.shared.global [%0], [%1], 16;" :: "r"(saddr), "l"(gptr))
#define CP4(saddr, gptr) \
    asm volatile("cp.async.ca.shared.global [%0], [%1], 4;" :: "r"(saddr), "l"(gptr))
#define CP_COMMIT() asm volatile("cp.async.commit_group;" ::: "memory")
#define CP_WAIT1()  asm volatile("cp.async.wait_group 1;" ::: "memory")
#define CP_WAIT0()  asm volatile("cp.async.wait_group 0;" ::: "memory")

constexpr int A_HI = 0;
constexpr int A_LO = 1032;
constexpr int B_HI = 2064;
constexpr int B_LO = 3096;
constexpr int STG  = 4128;          // u32 per MMA stage
constexpr int FA   = 12384;         // u32 offset of FFMA A stages (3 x 2048)
constexpr int FB   = 18528;         // u32 offset of FFMA B stages (3 x 512)
constexpr int HS_TOTAL = 20064;     // u32 total hybrid smem (80256 B)

// scalar split-fragment store: value pair (kg, kg+1) of row rl (within tile mt)
__device__ __forceinline__ void store_split(
    uint32_t* Csp, int KBC, int mt, int rl, int kg, float v0, float v1)
{
    uint32_t h, l;
    split2(v0, v1, h, l);
    int kb = kg >> 4, kk = kg & 15;
    int idx = (rl >> 4) * 128 + ((rl & 7) * 4 + ((kk & 7) >> 1)) * 4
            + ((rl >> 3) & 1) + 2 * (kk >> 3);
    size_t base = ((size_t)mt * KBC + kb) * 2048 + idx;
    Csp[base] = h;
    Csp[base + 1024] = l;
}

// ---------------- consume one MMA stage -----------------------------------
template<int NF>
__device__ __forceinline__ void consume_stage(
    const uint32_t* stg, float (&acc)[4][NF][4], int L, int wm, int wn)
{
    uint32_t ah[4][4], al[4][4], bh[NF][2], bl[NF][2];
    #pragma unroll
    for (int mf = 0; mf < 4; mf++) {
        const uint32_t* ab = stg + (wm * 4 + mf) * 128 + L * 4;
        *(uint4*)ah[mf] = *(const uint4*)(ab + A_HI);
        *(uint4*)al[mf] = *(const uint4*)(ab + A_LO);
    }
    #pragma unroll
    for (int nf = 0; nf < NF; nf++) {
        const uint32_t* bb = stg + (wn * NF + nf) * 64 + L * 2;
        *(uint2*)bh[nf] = *(const uint2*)(bb + B_HI);
        *(uint2*)bl[nf] = *(const uint2*)(bb + B_LO);
    }
    #pragma unroll
    for (int mf = 0; mf < 4; mf++)
        #pragma unroll
        for (int nf = 0; nf < NF; nf++)
            mma16(acc[mf][nf], ah[mf], bh[nf]);
    #pragma unroll
    for (int mf = 0; mf < 4; mf++)
        #pragma unroll
        for (int nf = 0; nf < NF; nf++)
            mma16(acc[mf][nf], ah[mf], bl[nf]);
    #pragma unroll
    for (int mf = 0; mf < 4; mf++)
        #pragma unroll
        for (int nf = 0; nf < NF; nf++)
            mma16(acc[mf][nf], al[mf], bh[nf]);
}

// ---------------- FFMA consume (f32, 8 rows x 4 cols per thread) ----------
__device__ __forceinline__ void ffma_consume(
    const uint32_t* smu, int stage, int r0, int c0, float (&accF)[8][4])
{
    const float* As = (const float*)(smu + FA + stage * 2048);   // [row][16]
    const float* Bs = (const float*)(smu + FB + stage * 512);    // [k][32]
    #pragma unroll
    for (int k4 = 0; k4 < 4; k4++) {
        float4 bk[4];
        #pragma unroll
        for (int kk = 0; kk < 4; kk++)
            bk[kk] = *(const float4*)(Bs + (k4 * 4 + kk) * 32 + c0);
        #pragma unroll
        for (int rr = 0; rr < 8; rr++) {
            float4 a4 = *(const float4*)(As + (r0 + rr) * 16 + k4 * 4);
            accF[rr][0] += a4.x * bk[0].x + a4.y * bk[1].x + a4.z * bk[2].x + a4.w * bk[3].x;
            accF[rr][1] += a4.x * bk[0].y + a4.y * bk[1].y + a4.z * bk[2].y + a4.w * bk[3].y;
            accF[rr][2] += a4.x * bk[0].z + a4.y * bk[1].z + a4.z * bk[2].z + a4.w * bk[3].z;
            accF[rr][3] += a4.x * bk[0].w + a4.y * bk[1].w + a4.z * bk[2].w + a4.w * bk[3].w;
        }
    }
}

// ================= hybrid MMA+FFMA GEMM for L2 / L3 =======================
// 384 threads: warps 0..7 = MMA (128 x 128*NF/4 cols), warps 8..11 = FFMA
// (128 x 32 f32 cols at offset 128). Tile width 160 (tile 6: 96, MMA-only).
// HEPI 2: bias+relu -> H2Sp split + H2f f32.  HEPI 5: relations -> rel.
template<int HEPI, int NF, int FF>
__device__ __forceinline__ void hybrid_body(
    const uint32_t* __restrict__ Asp, const float* __restrict__ Af,
    const uint32_t* __restrict__ Bsp, const float* __restrict__ Bf,
    float* __restrict__ Cf, uint32_t* __restrict__ Csp,
    const float* __restrict__ bias, uint32_t* smu)
{
    const int t = threadIdx.x;
    const int mt = blockIdx.y, m0 = mt * 128;
    const int n0 = blockIdx.x * 160;
    const int n0F = n0 + 128;
    const int KB = 66;
    const uint32_t sbase = smem_u32(smu);

    const int L = t & 31, wid = t >> 5;
    const int wm = (wid >> 2) & 1, wn = wid & 3;
    const int tf = t - 256;
    const int fr = tf >> 3, fc = tf & 7;
    const int r0 = fr * 8, c0 = fc * 4;

    union AccU {
        float a[4][NF][4];
        float f[8][4];
    } U;
    #pragma unroll
    for (int i = 0; i < 4; i++)
        #pragma unroll
        for (int j = 0; j < NF; j++)
            #pragma unroll
            for (int v = 0; v < 4; v++) U.a[i][j][v] = 0.f;

    auto copyasync = [&](int kb, int stage) {
        if (t < 256) {
            uint32_t s0 = sbase + (uint32_t)stage * STG * 4;
            const uint32_t* gA = Asp + ((size_t)(mt * KB + kb)) * 2048;
            CP16(s0 + (A_HI + t * 4) * 4, gA + t * 4);
            CP16(s0 + (A_LO + t * 4) * 4, gA + 1024 + t * 4);
            const uint32_t* gB = Bsp + ((size_t)(blockIdx.x * KB + kb)) * 2048;
            if (NF == 4) {
                CP16(s0 + (B_HI + t * 4) * 4, gB + t * 4);
                CP16(s0 + (B_LO + t * 4) * 4, gB + 1024 + t * 4);
            } else {
                if (t < 64 * NF) {
                    CP16(s0 + (B_HI + t * 4) * 4, gB + t * 4);
                    CP16(s0 + (B_LO + t * 4) * 4, gB + 1024 + t * 4);
                }
            }
        } else if (FF) {
            uint32_t s0a = sbase + (uint32_t)(FA + stage * 2048) * 4;
            #pragma unroll
            for (int i = 0; i < 4; i++) {
                int o = (tf * 4 + i) * 4;       // u32 offset in A stage
                int row = o >> 4, kp = o & 15;
                CP16(s0a + o * 4, Af + (size_t)(m0 + row) * TP + kb * 16 + kp);
            }
            uint32_t s0b = sbase + (uint32_t)(FB + stage * 512) * 4;
            int o = tf * 4;
            int k = o >> 5, col = o & 31;
            CP16(s0b + o * 4, Bf + (size_t)(kb * 16 + k) * TP + n0F + col);
        }
        CP_COMMIT();
    };

    copyasync(0, 0);
    copyasync(1, 1);
    int stage = 0;
    for (int kb = 0; kb < KB; kb++) {
        if (kb < KB - 1) CP_WAIT1(); else CP_WAIT0();
        __syncthreads();
        if (t < 256) consume_stage<NF>(smu + stage * STG, U.a, L, wm, wn);
        else if (FF) ffma_consume(smu, stage, r0, c0, U.f);
        if (kb + 2 < KB) {
            int ns = stage + 2;
            if (ns >= 3) ns -= 3;
            copyasync(kb + 2, ns);
        }
        stage = (stage + 1 == 3) ? 0 : stage + 1;
    }

    if (HEPI == 2) {
        if (t < 256) {
            #pragma unroll
            for (int mf = 0; mf < 4; mf++) {
                int rl = wm * 64 + mf * 16 + (L >> 2);
                #pragma unroll
                for (int nf = 0; nf < NF; nf++) {
                    int col = n0 + wn * 8 * NF + nf * 8 + (L & 3) * 2;
                    float2 b2 = *(const float2*)(bias + col);
                    float c0v = fmaxf(U.a[mf][nf][0] + b2.x, 0.f);
                    float c1v = fmaxf(U.a[mf][nf][1] + b2.y, 0.f);
                    float c2v = fmaxf(U.a[mf][nf][2] + b2.x, 0.f);
                    float c3v = fmaxf(U.a[mf][nf][3] + b2.y, 0.f);
                    store_split(Csp, 66, mt, rl, col, c0v, c1v);
                    store_split(Csp, 66, mt, rl + 8, col, c2v, c3v);
                    *(float2*)(Cf + (size_t)(m0 + rl) * TP + col)     = make_float2(c0v, c1v);
                    *(float2*)(Cf + (size_t)(m0 + rl + 8) * TP + col) = make_float2(c2v, c3v);
                }
            }
        } else if (FF) {
            float4 bv = *(const float4*)(bias + n0F + c0);
            float bb[4] = {bv.x, bv.y, bv.z, bv.w};
            #pragma unroll
            for (int rr = 0; rr < 8; rr++) {
                float v[4];
                #pragma unroll
                for (int cc = 0; cc < 4; cc++)
                    v[cc] = fmaxf(U.f[rr][cc] + bb[cc], 0.f);
                *(float4*)(Cf + (size_t)(m0 + r0 + rr) * TP + n0F + c0) =
                    make_float4(v[0], v[1], v[2], v[3]);
                store_split(Csp, 66, mt, r0 + rr, n0F + c0,     v[0], v[1]);
                store_split(Csp, 66, mt, r0 + rr, n0F + c0 + 2, v[2], v[3]);
            }
        }
        return;
    }

    // HEPI == 5: relations epilogue
    float* smf  = (float*)smu;          // MMA group sums [16][NF*32]
    float* smfF = smf + 2048;           // FFMA group sums [16][32]
    const int NFC = NF * 32;
    __syncthreads();
    if (t < 256) {
        #pragma unroll
        for (int mf = 0; mf < 4; mf++) {
            #pragma unroll
            for (int nf = 0; nf < NF; nf++) {
                int colL = wn * 8 * NF + nf * 8 + (L & 3) * 2;
                float2 b2 = *(const float2*)(bias + n0 + colL);
                float c0v = fmaxf(U.a[mf][nf][0] + b2.x, 0.f);
                float c1v = fmaxf(U.a[mf][nf][1] + b2.y, 0.f);
                float c2v = fmaxf(U.a[mf][nf][2] + b2.x, 0.f);
                float c3v = fmaxf(U.a[mf][nf][3] + b2.y, 0.f);
                c0v += __shfl_down_sync(0xffffffffu, c0v, 16);
                c0v += __shfl_down_sync(0xffffffffu, c0v, 8);
                c0v += __shfl_down_sync(0xffffffffu, c0v, 4);
                c1v += __shfl_down_sync(0xffffffffu, c1v, 16);
                c1v += __shfl_down_sync(0xffffffffu, c1v, 8);
                c1v += __shfl_down_sync(0xffffffffu, c1v, 4);
                c2v += __shfl_down_sync(0xffffffffu, c2v, 16);
                c2v += __shfl_down_sync(0xffffffffu, c2v, 8);
                c2v += __shfl_down_sync(0xffffffffu, c2v, 4);
                c3v += __shfl_down_sync(0xffffffffu, c3v, 16);
                c3v += __shfl_down_sync(0xffffffffu, c3v, 8);
                c3v += __shfl_down_sync(0xffffffffu, c3v, 4);
                if (L < 4) {
                    int gl = (wm * 64 + mf * 16) >> 3;
                    smf[gl * NFC + colL]           = c0v;
                    smf[gl * NFC + colL + 1]       = c1v;
                    smf[(gl + 1) * NFC + colL]     = c2v;
                    smf[(gl + 1) * NFC + colL + 1] = c3v;
                }
            }
        }
    } else if (FF) {
        float4 bv = *(const float4*)(bias + n0F + c0);
        float bb[4] = {bv.x, bv.y, bv.z, bv.w};
        #pragma unroll
        for (int cc = 0; cc < 4; cc++) {
            float s = 0.f;
            #pragma unroll
            for (int rr = 0; rr < 8; rr++)
                s += fmaxf(U.f[rr][cc] + bb[cc], 0.f);
            smfF[fr * 32 + c0 + cc] = s;
        }
    }
    __syncthreads();
    const int b = mt;
    if (NF == 4) {
        if (t < 256) {
            int colL = t & 127, ah = t >> 7;
            float cs = 0.f;
            #pragma unroll
            for (int k = 0; k < 8; k++) cs += smf[k * 128 + colL];
            #pragma unroll
            for (int ai = 0; ai < 4; ai++) {
                int a = ah * 4 + ai;
                Cf[(size_t)(b * 8 + a) * TP + n0 + colL] = cs + smf[(8 + a) * 128 + colL];
            }
        } else if (FF) {
            int colL = tf & 31, q = tf >> 5;
            float cs = 0.f;
            #pragma unroll
            for (int k = 0; k < 8; k++) cs += smfF[k * 32 + colL];
            #pragma unroll
            for (int ai = 0; ai < 2; ai++) {
                int a = q * 2 + ai;
                Cf[(size_t)(b * 8 + a) * TP + n0F + colL] = cs + smfF[(8 + a) * 32 + colL];
            }
        }
    } else {
        if (t < 96) {
            int colL = t;
            float cs = 0.f;
            #pragma unroll
            for (int k = 0; k < 8; k++) cs += smf[k * NFC + colL];
            #pragma unroll
            for (int a = 0; a < 8; a++)
                Cf[(size_t)(b * 8 + a) * TP + n0 + colL] = cs + smf[(8 + a) * NFC + colL];
        }
    }
}

template<int HEPI>
__global__ void __launch_bounds__(384, 1) hybrid_k(
    const uint32_t* __restrict__ Asp, const float* __restrict__ Af,
    const uint32_t* __restrict__ Bsp, const float* __restrict__ Bf,
    float* __restrict__ Cf, uint32_t* __restrict__ Csp,
    const float* __restrict__ bias)
{
    extern __shared__ uint32_t smu[];
    if (blockIdx.x == 6)
        hybrid_body<HEPI, 3, 0>(Asp, Af, Bsp, Bf, Cf, Csp, bias, smu);
    else
        hybrid_body<HEPI, 4, 1>(Asp, Af, Bsp, Bf, Cf, Csp, bias, smu);
}

// ================= old-style MMA GEMM (emb / P / Q / f) ===================
template<int EPI, int AOUT, int NF>
__device__ __forceinline__ void epilogue(
    float (&acc)[4][NF][4], int Ncols, float* C, int ldc,
    uint32_t* Csp, int KBC, const float* bias, const float* w2v,
    float* smf)
{
    const int t = threadIdx.x;
    const int m0 = blockIdx.y * 128, n0 = blockIdx.x * 128;
    const int L = t & 31, wid = t >> 5, wm = wid >> 2, wn = wid & 3;
    const int baseRow = m0 + wm * 64;

    if (EPI == 4) {
        float pr[4][2];
        #pragma unroll
        for (int mf = 0; mf < 4; mf++) { pr[mf][0] = 0.f; pr[mf][1] = 0.f; }
        #pragma unroll
        for (int mf = 0; mf < 4; mf++) {
            #pragma unroll
            for (int nf = 0; nf < NF; nf++) {
                int col = n0 + wn * 8 * NF + nf * 8 + (L & 3) * 2;
                float2 b2 = *(const float2*)(bias + col);
                float c0 = fmaxf(acc[mf][nf][0] + b2.x, 0.f);
                float c1 = fmaxf(acc[mf][nf][1] + b2.y, 0.f);
                float c2 = fmaxf(acc[mf][nf][2] + b2.x, 0.f);
                float c3 = fmaxf(acc[mf][nf][3] + b2.y, 0.f);
                float2 w = *(const float2*)(w2v + col);
                pr[mf][0] += c0 * w.x + c1 * w.y;
                pr[mf][1] += c2 * w.x + c3 * w.y;
            }
        }
        #pragma unroll
        for (int mf = 0; mf < 4; mf++) {
            pr[mf][0] += __shfl_xor_sync(0xffffffffu, pr[mf][0], 1);
            pr[mf][0] += __shfl_xor_sync(0xffffffffu, pr[mf][0], 2);
            pr[mf][1] += __shfl_xor_sync(0xffffffffu, pr[mf][1], 1);
            pr[mf][1] += __shfl_xor_sync(0xffffffffu, pr[mf][1], 2);
            if ((L & 3) == 0) {
                int row = baseRow + mf * 16 + (L >> 2);
                atomicAdd(C + row, pr[mf][0]);
                atomicAdd(C + row + 8, pr[mf][1]);
            }
        }
        return;
    }

    if (AOUT == 1) {
        const int mt = blockIdx.y;
        #pragma unroll
        for (int mf = 0; mf < 4; mf++) {
            int rl = wm * 64 + mf * 16 + (L >> 2);
            #pragma unroll
            for (int nf = 0; nf < NF; nf++) {
                int col = n0 + wn * 8 * NF + nf * 8 + (L & 3) * 2;
                if ((col >> 4) < KBC) {
                    float c0 = acc[mf][nf][0], c1 = acc[mf][nf][1];
                    float c2 = acc[mf][nf][2], c3 = acc[mf][nf][3];
                    if (EPI >= 1) {
                        float2 b2 = *(const float2*)(bias + col);
                        c0 += b2.x; c1 += b2.y; c2 += b2.x; c3 += b2.y;
                    }
                    if (EPI >= 2) {
                        c0 = fmaxf(c0, 0.f); c1 = fmaxf(c1, 0.f);
                        c2 = fmaxf(c2, 0.f); c3 = fmaxf(c3, 0.f);
                    }
                    store_split(Csp, KBC, mt, rl, col, c0, c1);
                    store_split(Csp, KBC, mt, rl + 8, col, c2, c3);
                }
            }
        }
        return;
    }

    #pragma unroll
    for (int mf = 0; mf < 4; mf++) {
        #pragma unroll
        for (int nf = 0; nf < NF; nf++) {
            int col = n0 + wn * 8 * NF + nf * 8 + (L & 3) * 2;
            bool cv = col < Ncols;
            float c0 = acc[mf][nf][0], c1 = acc[mf][nf][1];
            float c2 = acc[mf][nf][2], c3 = acc[mf][nf][3];
            if (EPI >= 1) {
                float2 b2 = cv ? *(const float2*)(bias + col) : make_float2(0.f, 0.f);
                c0 += b2.x; c1 += b2.y; c2 += b2.x; c3 += b2.y;
            }
            if (EPI >= 2) {
                c0 = fmaxf(c0, 0.f); c1 = fmaxf(c1, 0.f);
                c2 = fmaxf(c2, 0.f); c3 = fmaxf(c3, 0.f);
            }
            if (cv) {
                int row = baseRow + mf * 16 + (L >> 2);
                *(float2*)(C + (size_t)row * ldc + col)       = make_float2(c0, c1);
                *(float2*)(C + (size_t)(row + 8) * ldc + col) = make_float2(c2, c3);
            }
        }
    }
}

template<int EPI, int AOUT, int NF>
__device__ __forceinline__ void gemm_reg(
    const float* __restrict__ A, int lda,
    const uint32_t* __restrict__ Bsp,
    int Ncols, float* __restrict__ C, int ldc,
    uint32_t* __restrict__ Csp, int KBC,
    int K, const float* __restrict__ bias, const float* __restrict__ w2v,
    uint32_t* smu)
{
    const int t  = threadIdx.x;
    const int m0 = blockIdx.y * 128;
    const int KB = K >> 4;
    const int prow = t >> 1, pks = t & 1;
    const int p8 = prow & 7, rb8 = (prow >> 3) & 1, fb = prow >> 4;
    const float* ApA = A + (size_t)(m0 + prow) * lda + pks * 8;

    float va[8];
    uint4 hB, lB;
    const int L = t & 31, wid = t >> 5, wm = wid >> 2, wn = wid & 3;
    float acc[4][NF][4];
    #pragma unroll
    for (int i = 0; i < 4; i++)
        #pragma unroll
        for (int j = 0; j < NF; j++)
            #pragma unroll
            for (int v = 0; v < 4; v++) acc[i][j][v] = 0.f;

    auto ldtile = [&](int kb) {
        const uint32_t* gB = Bsp + ((size_t)(blockIdx.x * KB + kb)) * 2048;
        if (NF == 4) {
            hB = ((const uint4*)gB)[t];
            lB = ((const uint4*)gB)[256 + t];
        } else {
            hB.x = gB[t];
            lB.x = gB[1024 + t];
        }
        int k0 = kb * 16;
        float4 x0 = *(const float4*)(ApA + k0);
        float4 x1 = *(const float4*)(ApA + k0 + 4);
        va[0] = x0.x; va[1] = x0.y; va[2] = x0.z; va[3] = x0.w;
        va[4] = x1.x; va[5] = x1.y; va[6] = x1.z; va[7] = x1.w;
    };
    auto sttile = [&](uint32_t* stg) {
        if (NF == 4) {
            *(uint4*)(stg + B_HI + t * 4) = hB;
            *(uint4*)(stg + B_LO + t * 4) = lB;
        } else {
            stg[B_HI + t] = hB.x;
            stg[B_LO + t] = lB.x;
        }
        #pragma unroll
        for (int j = 0; j < 4; j++) {
            uint32_t h, l;
            split2(va[2 * j], va[2 * j + 1], h, l);
            int ai = fb * 128 + (p8 * 4 + j) * 4 + rb8 + 2 * pks;
            stg[A_HI + ai] = h;
            stg[A_LO + ai] = l;
        }
    };

    ldtile(0);
    sttile(smu);
    __syncthreads();
    for (int kb = 0; kb < KB; kb++) {
        if (kb + 1 < KB) ldtile(kb + 1);
        consume_stage<NF>(smu + (kb & 1) * STG, acc, L, wm, wn);
        if (kb + 1 < KB) sttile(smu + ((kb + 1) & 1) * STG);
        __syncthreads();
    }
    epilogue<EPI, AOUT, NF>(acc, Ncols, C, ldc, Csp, KBC, bias, w2v, (float*)smu);
}

template<int EPI, int AOUT, int NF>
__device__ __forceinline__ void gemm_cpa(
    const uint32_t* __restrict__ Asp,
    const uint32_t* __restrict__ Bsp,
    int Ncols, float* __restrict__ C, int ldc,
    uint32_t* __restrict__ Csp, int KBC,
    int K, const float* __restrict__ bias, const float* __restrict__ w2v,
    uint32_t* smu)
{
    const int t  = threadIdx.x;
    const int KB = K >> 4;
    const int L = t & 31, wid = t >> 5, wm = wid >> 2, wn = wid & 3;
    const uint32_t sbase = smem_u32(smu);

    float acc[4][NF][4];
    #pragma unroll
    for (int i = 0; i < 4; i++)
        #pragma unroll
        for (int j = 0; j < NF; j++)
            #pragma unroll
            for (int v = 0; v < 4; v++) acc[i][j][v] = 0.f;

    auto copyasync = [&](int kb, int stage) {
        uint32_t s0 = sbase + (uint32_t)stage * STG * 4;
        const uint32_t* gA = Asp + ((size_t)(blockIdx.y * KB + kb)) * 2048;
        const uint32_t* gB = Bsp + ((size_t)(blockIdx.x * KB + kb)) * 2048;
        CP16(s0 + (A_HI + t * 4) * 4, gA + t * 4);
        CP16(s0 + (A_LO + t * 4) * 4, gA + 1024 + t * 4);
        if (NF == 4) {
            CP16(s0 + (B_HI + t * 4) * 4, gB + t * 4);
            CP16(s0 + (B_LO + t * 4) * 4, gB + 1024 + t * 4);
        } else {
            CP4(s0 + (B_HI + t) * 4, gB + t);
            CP4(s0 + (B_LO + t) * 4, gB + 1024 + t);
        }
        CP_COMMIT();
    };

    copyasync(0, 0);
    copyasync(1, 1);
    int stage = 0;
    for (int kb = 0; kb < KB; kb++) {
        if (kb < KB - 1) CP_WAIT1(); else CP_WAIT0();
        __syncthreads();
        consume_stage<NF>(smu + stage * STG, acc, L, wm, wn);
        if (kb + 2 < KB) {
            int ns = stage + 2;
            if (ns >= 3) ns -= 3;
            copyasync(kb + 2, ns);
        }
        stage = (stage + 1 == 3) ? 0 : stage + 1;
    }
    epilogue<EPI, AOUT, NF>(acc, Ncols, C, ldc, Csp, KBC, bias, w2v, (float*)smu);
}

template<int EPI, int ASRC, int AOUT, int NARROW>
__global__ void __launch_bounds__(256, 1) mmagemm_k(
    const float* __restrict__ A, int lda,
    const uint32_t* __restrict__ Asp,
    const uint32_t* __restrict__ Bsp,
    int Ncols, float* __restrict__ C, int ldc,
    uint32_t* __restrict__ Csp, int KBC,
    int K, const float* __restrict__ bias, const float* __restrict__ w2v)
{
    extern __shared__ uint32_t smu[];
    if (ASRC == 2) {
        if (NARROW && blockIdx.x == gridDim.x - 1)
            gemm_cpa<EPI, AOUT, 1>(Asp, Bsp, Ncols, C, ldc, Csp, KBC, K, bias, w2v, smu);
        else
            gemm_cpa<EPI, AOUT, 4>(Asp, Bsp, Ncols, C, ldc, Csp, KBC, K, bias, w2v, smu);
    } else {
        if (NARROW && blockIdx.x == gridDim.x - 1)
            gemm_reg<EPI, AOUT, 1>(A, lda, Bsp, Ncols, C, ldc, Csp, KBC, K, bias, w2v, smu);
        else
            gemm_reg<EPI, AOUT, 4>(A, lda, Bsp, Ncols, C, ldc, Csp, KBC, K, bias, w2v, smu);
    }
}

// ---------------- x pre-split ---------------------------------------------
__global__ void xsplit_k(uint32_t* __restrict__ dst, const float* __restrict__ src)
{
    const int mt = blockIdx.y;
    const int t = threadIdx.x;
    const int prow = t >> 1, pks = t & 1;
    const int p8 = prow & 7, rb8 = (prow >> 3) & 1, fb = prow >> 4;
    const float* A = src + (size_t)(mt * 128 + prow) * KE + pks * 8;
    const int kb0 = blockIdx.x * 8;
    #pragma unroll 2
    for (int kb = kb0; kb < kb0 + 8; kb++) {
        float4 x0 = *(const float4*)(A + kb * 16);
        float4 x1 = *(const float4*)(A + kb * 16 + 4);
        float va[8] = {x0.x, x0.y, x0.z, x0.w, x1.x, x1.y, x1.z, x1.w};
        uint32_t* stg = dst + ((size_t)mt * 400 + kb) * 2048;
        #pragma unroll
        for (int j = 0; j < 4; j++) {
            uint32_t h, l;
            split2(va[2 * j], va[2 * j + 1], h, l);
            int ai = fb * 128 + (p8 * 4 + j) * 4 + rb8 + 2 * pks;
            stg[ai] = h;
            stg[1024 + ai] = l;
        }
    }
}

// ---------------- merged prep ---------------------------------------------
__device__ __forceinline__ void wsplit_body(
    uint32_t* dst, const float* src, int idx,
    int KB, int TW, int sK, int sN, int sStride, int rowOff)
{
    int bi  = idx & 1023;
    int pks = bi & 1;
    int lj  = (bi >> 1) & 31;
    int nb  = bi >> 6;
    int p8  = lj >> 2, j = lj & 3;
    int tile = idx >> 10;
    int nt = tile / KB, kb = tile % KB;
    int n = nt * TW + nb * 8 + p8;
    int k = kb * 16 + pks * 8 + 2 * j;
    float w0 = (k < sK && n < sN)     ? src[(size_t)(k + rowOff) * sStride + n]     : 0.f;
    float w1 = (k + 1 < sK && n < sN) ? src[(size_t)(k + 1 + rowOff) * sStride + n] : 0.f;
    uint32_t h, l;
    split2(w0, w1, h, l);
    dst[(size_t)tile * 2048 + bi] = h;
    dst[(size_t)tile * 2048 + 1024 + bi] = l;
}

__global__ void prep_k(
    uint32_t* __restrict__ WembSp, uint32_t* __restrict__ W1tSp,
    uint32_t* __restrict__ W1bSp, uint32_t* __restrict__ W2Sp,
    uint32_t* __restrict__ W3Sp, uint32_t* __restrict__ Wf1Sp,
    float* __restrict__ W2f, float* __restrict__ W3f,
    uint32_t* __restrict__ tsp,
    float* __restrict__ b1p, float* __restrict__ b2p, float* __restrict__ b3p,
    float* __restrict__ bf1p, float* __restrict__ Wf2p,
    const float* __restrict__ W_emb, const float* __restrict__ Wg1,
    const float* __restrict__ Wg2, const float* __restrict__ Wg3,
    const float* __restrict__ Wf1, const float* __restrict__ bg1,
    const float* __restrict__ bg2, const float* __restrict__ bg3,
    const float* __restrict__ bf1, const float* __restrict__ Wf2)
{
    int idx = blockIdx.x * blockDim.x + threadIdx.x;
    const int C0 = 4 * 400 * 1024;
    const int C1 = 9 * 33 * 1024;
    const int CW = 7 * 66 * 1024;
    const int CF1 = 9 * 66 * 1024;
    const int CP = TP * TP;
    const int C6 = 64 * 1024;

    if (idx < C0) { wsplit_body(WembSp, W_emb, idx, 400, 128, KE, 512, 512, 0); return; }
    idx -= C0;
    if (idx < C1) { wsplit_body(W1tSp, Wg1, idx, 33, 128, 521, T, T, 0); return; }
    idx -= C1;
    if (idx < C1) { wsplit_body(W1bSp, Wg1, idx, 33, 128, 521, T, T, 521); return; }
    idx -= C1;
    if (idx < CW) { wsplit_body(W2Sp, Wg2, idx, 66, 160, T, T, T, 0); return; }
    idx -= CW;
    if (idx < CW) { wsplit_body(W3Sp, Wg3, idx, 66, 160, T, T, T, 0); return; }
    idx -= CW;
    if (idx < CF1) { wsplit_body(Wf1Sp, Wf1, idx, 66, 128, T, T, T, 0); return; }
    idx -= CF1;
    if (idx < CP) {
        int r = idx / TP, c = idx % TP;
        W2f[idx] = (r < T && c < T) ? Wg2[(size_t)r * T + c] : 0.f;
        return;
    }
    idx -= CP;
    if (idx < CP) {
        int r = idx / TP, c = idx % TP;
        W3f[idx] = (r < T && c < T) ? Wg3[(size_t)r * T + c] : 0.f;
        return;
    }
    idx -= CP;
    if (idx < C6) {
        int ai = idx & 1023;
        int mt = idx >> 10;
        int w = ai & 127, fbv = ai >> 7;
        int lane = w >> 2, rem = w & 3;
        int rb8 = rem & 1, pks = rem >> 1;
        int p8 = lane >> 2, j = lane & 3;
        int r = mt * 128 + fbv * 16 + rb8 * 8 + p8;
        int col = 512 + pks * 8 + 2 * j;
        int tpos = ((r & 15) < 8) ? (r & 15) : 8;
        int tcol = 512 + tpos;
        uint32_t h = 0;
        if (col == tcol)     h |= 0x3F80u;
        if (col + 1 == tcol) h |= 0x3F80u << 16;
        size_t base = ((size_t)mt * 33 + 32) * 2048 + ai;
        tsp[base] = h;
        tsp[base + 1024] = 0u;
        return;
    }
    idx -= C6;
    if (idx < 5 * TP) {
        int v = idx / TP, c = idx % TP;
        const float* s = (v == 0) ? bg1 : (v == 1) ? bg2 : (v == 2) ? bg3
                       : (v == 3) ? bf1 : Wf2;
        float* d = (v == 0) ? b1p : (v == 1) ? b2p : (v == 2) ? b3p
                 : (v == 3) ? bf1p : Wf2p;
        d[c] = (c < T) ? s[c] : 0.f;
    }
}

// ---- H1 expand + split (H1Sp) + f32 copy (H1f) ---------------------------
__global__ void expandsp_k(const float* __restrict__ P, const float* __restrict__ Q,
                           const float* __restrict__ b1, uint32_t* __restrict__ H1sp,
                           float* __restrict__ H1f)
{
    __shared__ float sP[8][16], sQ[16][16], sB[16];
    int b = blockIdx.y, kb = blockIdx.x;
    int t = threadIdx.x;
    int k0 = kb * 16;
    if (t < 96) {
        int row = t >> 2, q = t & 3;
        const float* src = (row < 8) ? (P + (size_t)(b * 16 + row) * TP)
                                     : (Q + (size_t)(b * 16 + row - 8) * TP);
        float4 v = *(const float4*)(src + k0 + q * 4);
        if (row < 8) *(float4*)&sP[row][q * 4] = v;
        else         *(float4*)&sQ[row - 8][q * 4] = v;
    } else if (t < 100) {
        int q = t - 96;
        *(float4*)&sB[q * 4] = *(const float4*)(b1 + k0 + q * 4);
    }
    __syncthreads();
    int L = t & 31;
    int p8 = L >> 2, j = L & 3;
    int fbv = t >> 5;
    uint32_t hi[4], lo[4];
    #pragma unroll
    for (int s = 0; s < 2; s++) {
        int kA = s * 8 + 2 * j;
        #pragma unroll
        for (int rb = 0; rb < 2; rb++) {
            int r = fbv * 16 + rb * 8 + p8;
            int jj = r & 7, kk = r >> 3;
            float e0 = fmaxf(sP[jj][kA]     + sQ[kk][kA]     + sB[kA],     0.f);
            float e1 = fmaxf(sP[jj][kA + 1] + sQ[kk][kA + 1] + sB[kA + 1], 0.f);
            split2(e0, e1, hi[2 * s + rb], lo[2 * s + rb]);
            *(float2*)(H1f + (size_t)(b * 128 + r) * TP + k0 + kA) = make_float2(e0, e1);
        }
    }
    size_t base = ((size_t)b * 66 + kb) * 2048 + t * 4;
    *(uint4*)(H1sp + base)        = make_uint4(hi[0], hi[1], hi[2], hi[3]);
    *(uint4*)(H1sp + base + 1024) = make_uint4(lo[0], lo[1], lo[2], lo[3]);
}

// ======================= small kernels ====================================
__inline__ __device__ float warp_sum(float v)
{
    #pragma unroll
    for (int o = 16; o; o >>= 1) v += __shfl_down_sync(0xffffffffu, v, o);
    return v;
}

__global__ void loss_k(const float* __restrict__ fo, const int* __restrict__ labels,
                       const float* __restrict__ bf2, float* __restrict__ out)
{
    int b = threadIdx.x;
    int lab = labels[b];
    float bias2 = bf2[0];
    float lsum = 0.f;
    float best = -1e30f; int bi = 0;
    #pragma unroll
    for (int a = 0; a < 8; a++) {
        float f = fo[b * 8 + a] + bias2;
        float l = fmaxf(f, 0.f) - f * ((a == lab) ? 1.f : 0.f) + log1pf(expf(-fabsf(f)));
        lsum += l;
        if (f > best) { best = f; bi = a; }
    }
    float cor = (bi == lab) ? 1.f : 0.f;
    lsum = warp_sum(lsum);
    cor  = warp_sum(cor);
    __shared__ float sl[16], sc[16];
    int wid = threadIdx.x >> 5, lane = threadIdx.x & 31;
    if (lane == 0) { sl[wid] = lsum; sc[wid] = cor; }
    __syncthreads();
    if (wid == 0) {
        float a = (lane < 16) ? sl[lane] : 0.f;
        float c = (lane < 16) ? sc[lane] : 0.f;
        a = warp_sum(a);
        c = warp_sum(c);
        if (lane == 0) {
            out[0] = a / (float)(NBATCH * 8);
            out[1] = c / (float)NBATCH;
        }
    }
}

// ======================= host =============================================
static inline int cdiv(int a, int b) { return (a + b - 1) / b; }

extern "C" void kernel_launch(void* const* d_in, const int* in_sizes, int n_in,
                              void* d_out, int out_size)
{
    const float* x      = (const float*)d_in[0];
    const float* W_emb  = (const float*)d_in[1];
    const float* b_emb  = (const float*)d_in[2];
    const float* Wg1    = (const float*)d_in[3];
    const float* bg1    = (const float*)d_in[4];
    const float* Wg2    = (const float*)d_in[5];
    const float* bg2    = (const float*)d_in[6];
    const float* Wg3    = (const float*)d_in[7];
    const float* bg3    = (const float*)d_in[8];
    const float* Wf1    = (const float*)d_in[9];
    const float* bf1    = (const float*)d_in[10];
    const float* Wf2    = (const float*)d_in[11];
    const float* bf2    = (const float*)d_in[12];
    const int*   labels = (const int*)d_in[13];
    float* out = (float*)d_out;

    float *P, *Q, *rel, *fo, *H1f, *H2f, *W2f, *W3f;
    float *Wf2p, *b1p, *b2p, *b3p, *bf1p;
    uint32_t *xSp, *taggedSp, *H1Sp, *H2Sp, *WembSp, *W1tSp, *W1bSp, *W2Sp, *W3Sp, *Wf1Sp;
    cudaGetSymbolAddress((void**)&P, g_P);
    cudaGetSymbolAddress((void**)&Q, g_Q);
    cudaGetSymbolAddress((void**)&rel, g_rel);
    cudaGetSymbolAddress((void**)&fo, g_fo);
    cudaGetSymbolAddress((void**)&H1f, g_H1f);
    cudaGetSymbolAddress((void**)&H2f, g_H2f);
    cudaGetSymbolAddress((void**)&W2f, g_W2f);
    cudaGetSymbolAddress((void**)&W3f, g_W3f);
    cudaGetSymbolAddress((void**)&xSp, g_xSp);
    cudaGetSymbolAddress((void**)&taggedSp, g_taggedSp);
    cudaGetSymbolAddress((void**)&H1Sp, g_H1Sp);
    cudaGetSymbolAddress((void**)&H2Sp, g_H2Sp);
    cudaGetSymbolAddress((void**)&WembSp, g_WembSp);
    cudaGetSymbolAddress((void**)&W1tSp, g_W1tSp);
    cudaGetSymbolAddress((void**)&W1bSp, g_W1bSp);
    cudaGetSymbolAddress((void**)&W2Sp, g_W2Sp);
    cudaGetSymbolAddress((void**)&W3Sp, g_W3Sp);
    cudaGetSymbolAddress((void**)&Wf1Sp, g_Wf1Sp);
    cudaGetSymbolAddress((void**)&Wf2p, g_Wf2p);
    cudaGetSymbolAddress((void**)&b1p, g_b1);
    cudaGetSymbolAddress((void**)&b2p, g_b2);
    cudaGetSymbolAddress((void**)&b3p, g_b3);
    cudaGetSymbolAddress((void**)&bf1p, g_bf1);

    const int SMB2 = 2 * STG * 4;       // 33024 bytes (reg pipeline)
    const int SMB3 = 3 * STG * 4;       // 49536 bytes (cp.async pipeline)
    const int HSB  = HS_TOTAL * 4;      // 80256 bytes (hybrid)
    cudaFuncSetAttribute(mmagemm_k<1,2,1,0>, cudaFuncAttributeMaxDynamicSharedMemorySize, SMB3);
    cudaFuncSetAttribute(mmagemm_k<0,2,0,1>, cudaFuncAttributeMaxDynamicSharedMemorySize, SMB3);
    cudaFuncSetAttribute(mmagemm_k<4,0,0,1>, cudaFuncAttributeMaxDynamicSharedMemorySize, SMB2);
    cudaFuncSetAttribute(hybrid_k<2>, cudaFuncAttributeMaxDynamicSharedMemorySize, HSB);
    cudaFuncSetAttribute(hybrid_k<5>, cudaFuncAttributeMaxDynamicSharedMemorySize, HSB);

    // ---- one-time prep (1 launch) ----
    const int PREP_TOTAL = 4*400*1024 + 2*9*33*1024 + 2*7*66*1024 + 9*66*1024
                         + 2*TP*TP + 64*1024 + 5*TP;
    prep_k<<<cdiv(PREP_TOTAL, 256), 256>>>(
        WembSp, W1tSp, W1bSp, W2Sp, W3Sp, Wf1Sp, W2f, W3f, taggedSp,
        b1p, b2p, b3p, bf1p, Wf2p,
        W_emb, Wg1, Wg2, Wg3, Wf1, bg1, bg2, bg3, bf1, Wf2);
    xsplit_k<<<dim3(50, 64), 256>>>(xSp, x);
    cudaMemsetAsync(fo, 0, M_REL * sizeof(float));

    // emb = x @ W_emb + b_emb -> taggedSp
    mmagemm_k<1,2,1,0><<<dim3(4, M_EMB / 128), 256, SMB3>>>(
        nullptr, 0, xSp, WembSp, 512, nullptr, 0, taggedSp, 33, KE, b_emb, nullptr);
    // P / Q
    mmagemm_k<0,2,0,1><<<dim3(9, M_EMB / 128), 256, SMB3>>>(
        nullptr, 0, taggedSp, W1tSp, TP, P, TP, nullptr, 0, KT, nullptr, nullptr);
    mmagemm_k<0,2,0,1><<<dim3(9, M_EMB / 128), 256, SMB3>>>(
        nullptr, 0, taggedSp, W1bSp, TP, Q, TP, nullptr, 0, KT, nullptr, nullptr);
    // H1 expand -> H1Sp + H1f
    expandsp_k<<<dim3(66, NBATCH), 256>>>(P, Q, b1p, H1Sp, H1f);
    // L2 hybrid: H2 = relu(H1 @ Wg2 + b2) -> H2Sp + H2f
    hybrid_k<2><<<dim3(7, NBATCH), 384, HSB>>>(
        H1Sp, H1f, W2Sp, W2f, H2f, H2Sp, b2p);
    // L3 hybrid: relations -> rel
    hybrid_k<5><<<dim3(7, NBATCH), 384, HSB>>>(
        H2Sp, H2f, W3Sp, W3f, rel, nullptr, b3p);
    // f: Hf = relu(rel @ Wf1 + bf1); f_out fused -> fo
    mmagemm_k<4,0,0,1><<<dim3(9, M_REL / 128), 256, SMB2>>>(
        rel, TP, nullptr, Wf1Sp, TP, fo, TP, nullptr, 0, TP, bf1p, Wf2p);
    loss_k<<<1, 512>>>(fo, labels, bf2, out);
}

// round 15
// speedup vs baseline: 1.3252x; 1.3252x over previous
#include <cuda_runtime.h>
#include <cuda_bf16.h>
#include <cstdint>
#include <math.h>

#define NBATCH  512
#define T       1042
#define TP      1056
#define KE      6400
#define KT      528
#define M_EMB   8192
#define M_PAIR  65536
#define M_REL   4096

// ---------------- scratch (device globals; no allocation) ----------------
__device__ __align__(16) float g_P[(size_t)M_EMB * TP];
__device__ __align__(16) float g_Q[(size_t)M_EMB * TP];
__device__ __align__(16) float g_rel[(size_t)M_REL * TP];
__device__ __align__(16) float g_fo[M_REL];
// split (bf16 hi/lo, fragment-permuted) buffers: [tile][kb][limb][1024] u32
__device__ __align__(16) uint32_t g_xSp[(size_t)64 * 400 * 2048];
__device__ __align__(16) uint32_t g_taggedSp[(size_t)64 * 33 * 2048];
__device__ __align__(16) uint32_t g_H1Sp[(size_t)512 * 66 * 2048];
__device__ __align__(16) uint32_t g_H2Sp[(size_t)512 * 66 * 2048];
__device__ __align__(16) uint32_t g_WembSp[(size_t)4 * 400 * 2048];
__device__ __align__(16) uint32_t g_W1tSp[(size_t)9 * 33 * 2048];
__device__ __align__(16) uint32_t g_W1bSp[(size_t)9 * 33 * 2048];
__device__ __align__(16) uint32_t g_W2Sp[(size_t)9 * 66 * 2048];
__device__ __align__(16) uint32_t g_W3Sp[(size_t)9 * 66 * 2048];
__device__ __align__(16) uint32_t g_Wf1Sp[(size_t)9 * 66 * 2048];
__device__ __align__(16) float g_Wf2p[TP];
__device__ __align__(16) float g_b1[TP];
__device__ __align__(16) float g_b2[TP];
__device__ __align__(16) float g_b3[TP];
__device__ __align__(16) float g_bf1[TP];

// ---------------- helpers -------------------------------------------------
__device__ __forceinline__ void split2(float a, float b, uint32_t& h, uint32_t& l) {
    __nv_bfloat16 ha = __float2bfloat16(a);
    __nv_bfloat16 hb = __float2bfloat16(b);
    float fa = __bfloat162float(ha), fb = __bfloat162float(hb);
    __nv_bfloat16 la = __float2bfloat16(a - fa);
    __nv_bfloat16 lb = __float2bfloat16(b - fb);
    h = (uint32_t)__bfloat16_as_ushort(ha) | ((uint32_t)__bfloat16_as_ushort(hb) << 16);
    l = (uint32_t)__bfloat16_as_ushort(la) | ((uint32_t)__bfloat16_as_ushort(lb) << 16);
}

__device__ __forceinline__ void mma16(float acc[4], const uint32_t a[4], const uint32_t b[2]) {
    asm volatile(
        "mma.sync.aligned.m16n8k16.row.col.f32.bf16.bf16.f32 "
        "{%0,%1,%2,%3},{%4,%5,%6,%7},{%8,%9},{%0,%1,%2,%3};"
        : "+f"(acc[0]), "+f"(acc[1]), "+f"(acc[2]), "+f"(acc[3])
        : "r"(a[0]), "r"(a[1]), "r"(a[2]), "r"(a[3]), "r"(b[0]), "r"(b[1]));
}

__device__ __forceinline__ uint32_t smem_u32(const void* p) {
    uint32_t a;
    asm("{ .reg .u64 t; cvta.to.shared.u64 t, %1; cvt.u32.u64 %0, t; }" : "=r"(a) : "l"(p));
    return a;
}
#define CP16(saddr, gptr) \
    asm volatile("cp.async.cg.shared.global [%0], [%1], 16;" :: "r"(saddr), "l"(gptr))
#define CP4(saddr, gptr) \
    asm volatile("cp.async.ca.shared.global [%0], [%1], 4;" :: "r"(saddr), "l"(gptr))
#define CP_COMMIT() asm volatile("cp.async.commit_group;" ::: "memory")
#define CP_WAIT1()  asm volatile("cp.async.wait_group 1;" ::: "memory")
#define CP_WAIT0()  asm volatile("cp.async.wait_group 0;" ::: "memory")

constexpr int A_HI = 0;
constexpr int A_LO = 1032;
constexpr int B_HI = 2064;
constexpr int B_LO = 3096;
constexpr int STG  = 4128;          // u32 per stage

// ---------------- shared epilogue -----------------------------------------
// EPI: 0 plain store, 1 +bias, 2 +bias+relu  (AOUT selects f32 vs split)
//      4 bias+relu+dot(Wf2) -> atomicAdd fo   (C = fo)
//      5 bias+relu+8row-sum+relations -> rel  (C = rel, ldc = TP)
template<int EPI, int AOUT, int NF>
__device__ __forceinline__ void epilogue(
    int bx, float (&acc)[4][NF][4], int Ncols, float* C, int ldc,
    uint32_t* Csp, int KBC, const float* bias, const float* w2v,
    float* smf)
{
    const int t = threadIdx.x;
    const int m0 = blockIdx.y * 128, n0 = bx * 128;
    const int L = t & 31, wid = t >> 5, wm = wid >> 2, wn = wid & 3;
    const int baseRow = m0 + wm * 64;

    if (EPI == 4) {
        float pr[4][2];
        #pragma unroll
        for (int mf = 0; mf < 4; mf++) { pr[mf][0] = 0.f; pr[mf][1] = 0.f; }
        #pragma unroll
        for (int mf = 0; mf < 4; mf++) {
            #pragma unroll
            for (int nf = 0; nf < NF; nf++) {
                int col = n0 + wn * 8 * NF + nf * 8 + (L & 3) * 2;
                float2 b2 = *(const float2*)(bias + col);
                float c0 = fmaxf(acc[mf][nf][0] + b2.x, 0.f);
                float c1 = fmaxf(acc[mf][nf][1] + b2.y, 0.f);
                float c2 = fmaxf(acc[mf][nf][2] + b2.x, 0.f);
                float c3 = fmaxf(acc[mf][nf][3] + b2.y, 0.f);
                float2 w = *(const float2*)(w2v + col);
                pr[mf][0] += c0 * w.x + c1 * w.y;
                pr[mf][1] += c2 * w.x + c3 * w.y;
            }
        }
        #pragma unroll
        for (int mf = 0; mf < 4; mf++) {
            pr[mf][0] += __shfl_xor_sync(0xffffffffu, pr[mf][0], 1);
            pr[mf][0] += __shfl_xor_sync(0xffffffffu, pr[mf][0], 2);
            pr[mf][1] += __shfl_xor_sync(0xffffffffu, pr[mf][1], 1);
            pr[mf][1] += __shfl_xor_sync(0xffffffffu, pr[mf][1], 2);
            if ((L & 3) == 0) {
                int row = baseRow + mf * 16 + (L >> 2);
                atomicAdd(C + row, pr[mf][0]);
                atomicAdd(C + row + 8, pr[mf][1]);
            }
        }
        return;
    }

    if (EPI == 5) {
        const int NFC = NF * 32;
        __syncthreads();                    // stages fully consumed before smem reuse
        #pragma unroll
        for (int mf = 0; mf < 4; mf++) {
            #pragma unroll
            for (int nf = 0; nf < NF; nf++) {
                int colL = wn * 8 * NF + nf * 8 + (L & 3) * 2;
                float2 b2 = *(const float2*)(bias + n0 + colL);
                float c0 = fmaxf(acc[mf][nf][0] + b2.x, 0.f);
                float c1 = fmaxf(acc[mf][nf][1] + b2.y, 0.f);
                float c2 = fmaxf(acc[mf][nf][2] + b2.x, 0.f);
                float c3 = fmaxf(acc[mf][nf][3] + b2.y, 0.f);
                c0 += __shfl_down_sync(0xffffffffu, c0, 16);
                c0 += __shfl_down_sync(0xffffffffu, c0, 8);
                c0 += __shfl_down_sync(0xffffffffu, c0, 4);
                c1 += __shfl_down_sync(0xffffffffu, c1, 16);
                c1 += __shfl_down_sync(0xffffffffu, c1, 8);
                c1 += __shfl_down_sync(0xffffffffu, c1, 4);
                c2 += __shfl_down_sync(0xffffffffu, c2, 16);
                c2 += __shfl_down_sync(0xffffffffu, c2, 8);
                c2 += __shfl_down_sync(0xffffffffu, c2, 4);
                c3 += __shfl_down_sync(0xffffffffu, c3, 16);
                c3 += __shfl_down_sync(0xffffffffu, c3, 8);
                c3 += __shfl_down_sync(0xffffffffu, c3, 4);
                if (L < 4) {
                    int gl = (wm * 64 + mf * 16) >> 3;      // 0,2,4,...,14
                    smf[gl * NFC + colL]           = c0;
                    smf[gl * NFC + colL + 1]       = c1;
                    smf[(gl + 1) * NFC + colL]     = c2;
                    smf[(gl + 1) * NFC + colL + 1] = c3;
                }
            }
        }
        __syncthreads();
        const int b = blockIdx.y;
        if (NF == 4) {
            int colL = t & 127, ah = t >> 7;
            float cs = 0.f;
            #pragma unroll
            for (int k = 0; k < 8; k++) cs += smf[k * 128 + colL];
            #pragma unroll
            for (int ai = 0; ai < 4; ai++) {
                int a = ah * 4 + ai;
                C[(size_t)(b * 8 + a) * ldc + n0 + colL] = cs + smf[(8 + a) * 128 + colL];
            }
        } else {
            int colL = t & 31, a = t >> 5;
            float cs = 0.f;
            #pragma unroll
            for (int k = 0; k < 8; k++) cs += smf[k * 32 + colL];
            C[(size_t)(b * 8 + a) * ldc + n0 + colL] = cs + smf[(8 + a) * 32 + colL];
        }
        return;
    }

    if (AOUT == 1) {
        const int mt = blockIdx.y;
        if (NF == 4) {
            #pragma unroll
            for (int mf = 0; mf < 4; mf++) {
                #pragma unroll
                for (int f = 0; f < 2; f++) {
                    int kbC = (n0 >> 4) + wn * 2 + f;
                    if (kbC < KBC) {
                        uint32_t hi[4], lo[4];
                        #pragma unroll
                        for (int s = 0; s < 2; s++) {
                            int nf = 2 * f + s;
                            int col = n0 + wn * 32 + nf * 8 + (L & 3) * 2;
                            float c0 = acc[mf][nf][0], c1 = acc[mf][nf][1];
                            float c2 = acc[mf][nf][2], c3 = acc[mf][nf][3];
                            if (EPI >= 1) {
                                float2 b2 = *(const float2*)(bias + col);
                                c0 += b2.x; c1 += b2.y; c2 += b2.x; c3 += b2.y;
                            }
                            if (EPI >= 2) {
                                c0 = fmaxf(c0, 0.f); c1 = fmaxf(c1, 0.f);
                                c2 = fmaxf(c2, 0.f); c3 = fmaxf(c3, 0.f);
                            }
                            split2(c0, c1, hi[2 * s], lo[2 * s]);
                            split2(c2, c3, hi[2 * s + 1], lo[2 * s + 1]);
                        }
                        size_t base = ((size_t)mt * KBC + kbC) * 2048 + (wm * 4 + mf) * 128 + L * 4;
                        *(uint4*)(Csp + base)        = make_uint4(hi[0], hi[1], hi[2], hi[3]);
                        *(uint4*)(Csp + base + 1024) = make_uint4(lo[0], lo[1], lo[2], lo[3]);
                    }
                }
            }
        } else {
            #pragma unroll
            for (int mf = 0; mf < 4; mf++) {
                int col = n0 + wn * 8 + (L & 3) * 2;
                float c0 = acc[mf][0][0], c1 = acc[mf][0][1];
                float c2 = acc[mf][0][2], c3 = acc[mf][0][3];
                if (EPI >= 1) {
                    float2 b2 = *(const float2*)(bias + col);
                    c0 += b2.x; c1 += b2.y; c2 += b2.x; c3 += b2.y;
                }
                if (EPI >= 2) {
                    c0 = fmaxf(c0, 0.f); c1 = fmaxf(c1, 0.f);
                    c2 = fmaxf(c2, 0.f); c3 = fmaxf(c3, 0.f);
                }
                uint32_t h0, l0, h1, l1;
                split2(c0, c1, h0, l0);
                split2(c2, c3, h1, l1);
                int kbC = (n0 >> 4) + (wn >> 1);
                size_t base = ((size_t)mt * KBC + kbC) * 2048 + (wm * 4 + mf) * 128
                            + L * 4 + 2 * (wn & 1);
                *(uint2*)(Csp + base)        = make_uint2(h0, h1);
                *(uint2*)(Csp + base + 1024) = make_uint2(l0, l1);
            }
        }
        return;
    }

    #pragma unroll
    for (int mf = 0; mf < 4; mf++) {
        #pragma unroll
        for (int nf = 0; nf < NF; nf++) {
            int col = n0 + wn * 8 * NF + nf * 8 + (L & 3) * 2;
            bool cv = col < Ncols;
            float c0 = acc[mf][nf][0], c1 = acc[mf][nf][1];
            float c2 = acc[mf][nf][2], c3 = acc[mf][nf][3];
            if (EPI >= 1) {
                float2 b2 = cv ? *(const float2*)(bias + col) : make_float2(0.f, 0.f);
                c0 += b2.x; c1 += b2.y; c2 += b2.x; c3 += b2.y;
            }
            if (EPI >= 2) {
                c0 = fmaxf(c0, 0.f); c1 = fmaxf(c1, 0.f);
                c2 = fmaxf(c2, 0.f); c3 = fmaxf(c3, 0.f);
            }
            if (cv) {
                int row = baseRow + mf * 16 + (L >> 2);
                *(float2*)(C + (size_t)row * ldc + col)       = make_float2(c0, c1);
                *(float2*)(C + (size_t)(row + 8) * ldc + col) = make_float2(c2, c3);
            }
        }
    }
}

// ---------------- consume one stage ---------------------------------------
template<int NF>
__device__ __forceinline__ void consume_stage(
    const uint32_t* stg, float (&acc)[4][NF][4], int L, int wm, int wn)
{
    uint32_t ah[4][4], al[4][4], bh[NF][2], bl[NF][2];
    #pragma unroll
    for (int mf = 0; mf < 4; mf++) {
        const uint32_t* ab = stg + (wm * 4 + mf) * 128 + L * 4;
        *(uint4*)ah[mf] = *(const uint4*)(ab + A_HI);
        *(uint4*)al[mf] = *(const uint4*)(ab + A_LO);
    }
    #pragma unroll
    for (int nf = 0; nf < NF; nf++) {
        const uint32_t* bb = stg + (wn * NF + nf) * 64 + L * 2;
        *(uint2*)bh[nf] = *(const uint2*)(bb + B_HI);
        *(uint2*)bl[nf] = *(const uint2*)(bb + B_LO);
    }
    #pragma unroll
    for (int mf = 0; mf < 4; mf++)
        #pragma unroll
        for (int nf = 0; nf < NF; nf++) {
            mma16(acc[mf][nf], ah[mf], bh[nf]);
            mma16(acc[mf][nf], ah[mf], bl[nf]);
            mma16(acc[mf][nf], al[mf], bh[nf]);
        }
}

// ---------------- reg-pipeline body (A = f32, split on the fly) -----------
template<int EPI, int AOUT, int NF>
__device__ __forceinline__ void gemm_reg(
    int bx, const float* __restrict__ A, int lda,
    const uint32_t* __restrict__ Bsp,
    int Ncols, float* __restrict__ C, int ldc,
    uint32_t* __restrict__ Csp, int KBC,
    int K, const float* __restrict__ bias, const float* __restrict__ w2v,
    uint32_t* smu)
{
    const int t  = threadIdx.x;
    const int m0 = blockIdx.y * 128;
    const int KB = K >> 4;
    const int prow = t >> 1, pks = t & 1;
    const int p8 = prow & 7, rb8 = (prow >> 3) & 1, fb = prow >> 4;
    const float* ApA = A + (size_t)(m0 + prow) * lda + pks * 8;

    float va[8];
    uint4 hB, lB;
    const int L = t & 31, wid = t >> 5, wm = wid >> 2, wn = wid & 3;
    float acc[4][NF][4];
    #pragma unroll
    for (int i = 0; i < 4; i++)
        #pragma unroll
        for (int j = 0; j < NF; j++)
            #pragma unroll
            for (int v = 0; v < 4; v++) acc[i][j][v] = 0.f;

    auto ldtile = [&](int kb) {
        const uint32_t* gB = Bsp + ((size_t)(bx * KB + kb)) * 2048;
        if (NF == 4) {
            hB = ((const uint4*)gB)[t];
            lB = ((const uint4*)gB)[256 + t];
        } else {
            hB.x = gB[t];
            lB.x = gB[1024 + t];
        }
        int k0 = kb * 16;
        float4 x0 = *(const float4*)(ApA + k0);
        float4 x1 = *(const float4*)(ApA + k0 + 4);
        va[0] = x0.x; va[1] = x0.y; va[2] = x0.z; va[3] = x0.w;
        va[4] = x1.x; va[5] = x1.y; va[6] = x1.z; va[7] = x1.w;
    };
    auto sttile = [&](uint32_t* stg) {
        if (NF == 4) {
            *(uint4*)(stg + B_HI + t * 4) = hB;
            *(uint4*)(stg + B_LO + t * 4) = lB;
        } else {
            stg[B_HI + t] = hB.x;
            stg[B_LO + t] = lB.x;
        }
        #pragma unroll
        for (int j = 0; j < 4; j++) {
            uint32_t h, l;
            split2(va[2 * j], va[2 * j + 1], h, l);
            int ai = fb * 128 + (p8 * 4 + j) * 4 + rb8 + 2 * pks;
            stg[A_HI + ai] = h;
            stg[A_LO + ai] = l;
        }
    };

    ldtile(0);
    sttile(smu);
    __syncthreads();
    for (int kb = 0; kb < KB; kb++) {
        if (kb + 1 < KB) ldtile(kb + 1);
        consume_stage<NF>(smu + (kb & 1) * STG, acc, L, wm, wn);
        if (kb + 1 < KB) sttile(smu + ((kb + 1) & 1) * STG);
        __syncthreads();
    }
    epilogue<EPI, AOUT, NF>(bx, acc, Ncols, C, ldc, Csp, KBC, bias, w2v, (float*)smu);
}

// ---------------- cp.async 3-stage body (A pre-split, pure copy) ----------
template<int EPI, int AOUT, int NF>
__device__ __forceinline__ void gemm_cpa(
    int bx, const uint32_t* __restrict__ Asp,
    const uint32_t* __restrict__ Bsp,
    int Ncols, float* __restrict__ C, int ldc,
    uint32_t* __restrict__ Csp, int KBC,
    int K, const float* __restrict__ bias, const float* __restrict__ w2v,
    uint32_t* smu)
{
    const int t  = threadIdx.x;
    const int KB = K >> 4;
    const int L = t & 31, wid = t >> 5, wm = wid >> 2, wn = wid & 3;
    const uint32_t sbase = smem_u32(smu);

    float acc[4][NF][4];
    #pragma unroll
    for (int i = 0; i < 4; i++)
        #pragma unroll
        for (int j = 0; j < NF; j++)
            #pragma unroll
            for (int v = 0; v < 4; v++) acc[i][j][v] = 0.f;

    auto copyasync = [&](int kb, int stage) {
        uint32_t s0 = sbase + (uint32_t)stage * STG * 4;
        const uint32_t* gA = Asp + ((size_t)(blockIdx.y * KB + kb)) * 2048;
        const uint32_t* gB = Bsp + ((size_t)(bx * KB + kb)) * 2048;
        CP16(s0 + (A_HI + t * 4) * 4, gA + t * 4);
        CP16(s0 + (A_LO + t * 4) * 4, gA + 1024 + t * 4);
        if (NF == 4) {
            CP16(s0 + (B_HI + t * 4) * 4, gB + t * 4);
            CP16(s0 + (B_LO + t * 4) * 4, gB + 1024 + t * 4);
        } else {
            CP4(s0 + (B_HI + t) * 4, gB + t);
            CP4(s0 + (B_LO + t) * 4, gB + 1024 + t);
        }
        CP_COMMIT();
    };

    copyasync(0, 0);
    copyasync(1, 1);
    int stage = 0;
    for (int kb = 0; kb < KB; kb++) {
        if (kb < KB - 1) CP_WAIT1(); else CP_WAIT0();
        __syncthreads();
        consume_stage<NF>(smu + stage * STG, acc, L, wm, wn);
        if (kb + 2 < KB) {
            int ns = stage + 2;
            if (ns >= 3) ns -= 3;
            copyasync(kb + 2, ns);
        }
        stage = (stage + 1 == 3) ? 0 : stage + 1;
    }
    epilogue<EPI, AOUT, NF>(bx, acc, Ncols, C, ldc, Csp, KBC, bias, w2v, (float*)smu);
}

// ---------------- kernels -------------------------------------------------
template<int EPI, int ASRC, int AOUT, int NARROW>
__global__ void __launch_bounds__(256, 1) mmagemm_k(
    const float* __restrict__ A, int lda,
    const uint32_t* __restrict__ Asp,
    const uint32_t* __restrict__ Bsp,
    int Ncols, float* __restrict__ C, int ldc,
    uint32_t* __restrict__ Csp, int KBC,
    int K, const float* __restrict__ bias, const float* __restrict__ w2v)
{
    extern __shared__ uint32_t smu[];
    const int bx = blockIdx.x;
    if (ASRC == 2) {
        if (NARROW && bx == gridDim.x - 1)
            gemm_cpa<EPI, AOUT, 1>(bx, Asp, Bsp, Ncols, C, ldc, Csp, KBC, K, bias, w2v, smu);
        else
            gemm_cpa<EPI, AOUT, 4>(bx, Asp, Bsp, Ncols, C, ldc, Csp, KBC, K, bias, w2v, smu);
    } else {
        if (NARROW && bx == gridDim.x - 1)
            gemm_reg<EPI, AOUT, 1>(bx, A, lda, Bsp, Ncols, C, ldc, Csp, KBC, K, bias, w2v, smu);
        else
            gemm_reg<EPI, AOUT, 4>(bx, A, lda, Bsp, Ncols, C, ldc, Csp, KBC, K, bias, w2v, smu);
    }
}

// P and Q GEMMs merged in one launch: grid (18, 64).
// bx 0..8 -> P = tagged @ W1t ; bx 9..17 -> Q = tagged @ W1b. Narrow tile at bx%9==8.
__global__ void __launch_bounds__(256, 1) pqgemm_k(
    const uint32_t* __restrict__ Asp,
    const uint32_t* __restrict__ W1t, const uint32_t* __restrict__ W1b,
    float* __restrict__ P, float* __restrict__ Q)
{
    extern __shared__ uint32_t smu[];
    const bool isQ = blockIdx.x >= 9;
    const int bx = isQ ? blockIdx.x - 9 : blockIdx.x;
    const uint32_t* Bsp = isQ ? W1b : W1t;
    float* C = isQ ? Q : P;
    if (bx == 8)
        gemm_cpa<0, 0, 1>(bx, Asp, Bsp, TP, C, TP, nullptr, 0, KT, nullptr, nullptr, smu);
    else
        gemm_cpa<0, 0, 4>(bx, Asp, Bsp, TP, C, TP, nullptr, 0, KT, nullptr, nullptr, smu);
}

// ---------------- x pre-split: f32 -> A-fragment split layout -------------
__global__ void xsplit_k(uint32_t* __restrict__ dst, const float* __restrict__ src)
{
    const int mt = blockIdx.y;
    const int t = threadIdx.x;
    const int prow = t >> 1, pks = t & 1;
    const int p8 = prow & 7, rb8 = (prow >> 3) & 1, fb = prow >> 4;
    const float* A = src + (size_t)(mt * 128 + prow) * KE + pks * 8;
    const int kb0 = blockIdx.x * 8;
    #pragma unroll 2
    for (int kb = kb0; kb < kb0 + 8; kb++) {
        float4 x0 = *(const float4*)(A + kb * 16);
        float4 x1 = *(const float4*)(A + kb * 16 + 4);
        float va[8] = {x0.x, x0.y, x0.z, x0.w, x1.x, x1.y, x1.z, x1.w};
        uint32_t* stg = dst + ((size_t)mt * 400 + kb) * 2048;
        #pragma unroll
        for (int j = 0; j < 4; j++) {
            uint32_t h, l;
            split2(va[2 * j], va[2 * j + 1], h, l);
            int ai = fb * 128 + (p8 * 4 + j) * 4 + rb8 + 2 * pks;
            stg[ai] = h;
            stg[1024 + ai] = l;
        }
    }
}

// ---------------- merged prep: all weight splits + tags + bias pads -------
__device__ __forceinline__ void wsplit_body(
    uint32_t* dst, const float* src, int idx,
    int KB, int sK, int sN, int sStride, int rowOff)
{
    int bi  = idx & 1023;
    int pks = bi & 1;
    int lj  = (bi >> 1) & 31;
    int nb  = bi >> 6;
    int p8  = lj >> 2, j = lj & 3;
    int tile = idx >> 10;
    int nt = tile / KB, kb = tile % KB;
    int n = nt * 128 + nb * 8 + p8;
    int k = kb * 16 + pks * 8 + 2 * j;
    float w0 = (k < sK && n < sN)     ? src[(size_t)(k + rowOff) * sStride + n]     : 0.f;
    float w1 = (k + 1 < sK && n < sN) ? src[(size_t)(k + 1 + rowOff) * sStride + n] : 0.f;
    uint32_t h, l;
    split2(w0, w1, h, l);
    dst[(size_t)tile * 2048 + bi] = h;
    dst[(size_t)tile * 2048 + 1024 + bi] = l;
}

__global__ void prep_k(
    uint32_t* __restrict__ WembSp, uint32_t* __restrict__ W1tSp,
    uint32_t* __restrict__ W1bSp, uint32_t* __restrict__ W2Sp,
    uint32_t* __restrict__ W3Sp, uint32_t* __restrict__ Wf1Sp,
    uint32_t* __restrict__ tsp,
    float* __restrict__ b1p, float* __restrict__ b2p, float* __restrict__ b3p,
    float* __restrict__ bf1p, float* __restrict__ Wf2p,
    const float* __restrict__ W_emb, const float* __restrict__ Wg1,
    const float* __restrict__ Wg2, const float* __restrict__ Wg3,
    const float* __restrict__ Wf1, const float* __restrict__ bg1,
    const float* __restrict__ bg2, const float* __restrict__ bg3,
    const float* __restrict__ bf1, const float* __restrict__ Wf2)
{
    int idx = blockIdx.x * blockDim.x + threadIdx.x;
    const int C0 = 4 * 400 * 1024;
    const int C1 = 9 * 33 * 1024;
    const int C3 = 9 * 66 * 1024;
    const int C6 = 64 * 1024;

    if (idx < C0) { wsplit_body(WembSp, W_emb, idx, 400, KE, 512, 512, 0); return; }
    idx -= C0;
    if (idx < C1) { wsplit_body(W1tSp, Wg1, idx, 33, 521, T, T, 0); return; }
    idx -= C1;
    if (idx < C1) { wsplit_body(W1bSp, Wg1, idx, 33, 521, T, T, 521); return; }
    idx -= C1;
    if (idx < C3) { wsplit_body(W2Sp, Wg2, idx, 66, T, T, T, 0); return; }
    idx -= C3;
    if (idx < C3) { wsplit_body(W3Sp, Wg3, idx, 66, T, T, T, 0); return; }
    idx -= C3;
    if (idx < C3) { wsplit_body(Wf1Sp, Wf1, idx, 66, T, T, T, 0); return; }
    idx -= C3;
    if (idx < C6) {
        int ai = idx & 1023;
        int mt = idx >> 10;
        int w = ai & 127, fbv = ai >> 7;
        int lane = w >> 2, rem = w & 3;
        int rb8 = rem & 1, pks = rem >> 1;
        int p8 = lane >> 2, j = lane & 3;
        int r = mt * 128 + fbv * 16 + rb8 * 8 + p8;
        int col = 512 + pks * 8 + 2 * j;
        int tpos = ((r & 15) < 8) ? (r & 15) : 8;
        int tcol = 512 + tpos;
        uint32_t h = 0;
        if (col == tcol)     h |= 0x3F80u;
        if (col + 1 == tcol) h |= 0x3F80u << 16;
        size_t base = ((size_t)mt * 33 + 32) * 2048 + ai;
        tsp[base] = h;
        tsp[base + 1024] = 0u;
        return;
    }
    idx -= C6;
    if (idx < 5 * TP) {
        int v = idx / TP, c = idx % TP;
        const float* s = (v == 0) ? bg1 : (v == 1) ? bg2 : (v == 2) ? bg3
                       : (v == 3) ? bf1 : Wf2;
        float* d = (v == 0) ? b1p : (v == 1) ? b2p : (v == 2) ? b3p
                 : (v == 3) ? bf1p : Wf2p;
        d[c] = (c < T) ? s[c] : 0.f;
    }
}

// ---- H1 expand + split: relu(P[b,j]+Q[b,k]+b1) -> H1Sp -------------------
__global__ void expandsp_k(const float* __restrict__ P, const float* __restrict__ Q,
                           const float* __restrict__ b1, uint32_t* __restrict__ H1sp)
{
    __shared__ float sP[8][16], sQ[16][16], sB[16];
    int b = blockIdx.y, kb = blockIdx.x;
    int t = threadIdx.x;
    int k0 = kb * 16;
    if (t < 96) {
        int row = t >> 2, q = t & 3;
        const float* src = (row < 8) ? (P + (size_t)(b * 16 + row) * TP)
                                     : (Q + (size_t)(b * 16 + row - 8) * TP);
        float4 v = *(const float4*)(src + k0 + q * 4);
        if (row < 8) *(float4*)&sP[row][q * 4] = v;
        else         *(float4*)&sQ[row - 8][q * 4] = v;
    } else if (t < 100) {
        int q = t - 96;
        *(float4*)&sB[q * 4] = *(const float4*)(b1 + k0 + q * 4);
    }
    __syncthreads();
    int L = t & 31;
    int p8 = L >> 2, j = L & 3;
    int fbv = t >> 5;
    uint32_t hi[4], lo[4];
    #pragma unroll
    for (int s = 0; s < 2; s++) {
        int kA = s * 8 + 2 * j;
        #pragma unroll
        for (int rb = 0; rb < 2; rb++) {
            int r = fbv * 16 + rb * 8 + p8;
            int jj = r & 7, kk = r >> 3;
            float e0 = fmaxf(sP[jj][kA]     + sQ[kk][kA]     + sB[kA],     0.f);
            float e1 = fmaxf(sP[jj][kA + 1] + sQ[kk][kA + 1] + sB[kA + 1], 0.f);
            split2(e0, e1, hi[2 * s + rb], lo[2 * s + rb]);
        }
    }
    size_t base = ((size_t)b * 66 + kb) * 2048 + t * 4;
    *(uint4*)(H1sp + base)        = make_uint4(hi[0], hi[1], hi[2], hi[3]);
    *(uint4*)(H1sp + base + 1024) = make_uint4(lo[0], lo[1], lo[2], lo[3]);
}

// ======================= small kernels ====================================
__inline__ __device__ float warp_sum(float v)
{
    #pragma unroll
    for (int o = 16; o; o >>= 1) v += __shfl_down_sync(0xffffffffu, v, o);
    return v;
}

__global__ void loss_k(const float* __restrict__ fo, const int* __restrict__ labels,
                       const float* __restrict__ bf2, float* __restrict__ out)
{
    int b = threadIdx.x;
    int lab = labels[b];
    float bias2 = bf2[0];
    float lsum = 0.f;
    float best = -1e30f; int bi = 0;
    #pragma unroll
    for (int a = 0; a < 8; a++) {
        float f = fo[b * 8 + a] + bias2;
        float l = fmaxf(f, 0.f) - f * ((a == lab) ? 1.f : 0.f) + log1pf(expf(-fabsf(f)));
        lsum += l;
        if (f > best) { best = f; bi = a; }
    }
    float cor = (bi == lab) ? 1.f : 0.f;
    lsum = warp_sum(lsum);
    cor  = warp_sum(cor);
    __shared__ float sl[16], sc[16];
    int wid = threadIdx.x >> 5, lane = threadIdx.x & 31;
    if (lane == 0) { sl[wid] = lsum; sc[wid] = cor; }
    __syncthreads();
    if (wid == 0) {
        float a = (lane < 16) ? sl[lane] : 0.f;
        float c = (lane < 16) ? sc[lane] : 0.f;
        a = warp_sum(a);
        c = warp_sum(c);
        if (lane == 0) {
            out[0] = a / (float)(NBATCH * 8);
            out[1] = c / (float)NBATCH;
        }
    }
}

// ======================= host =============================================
static inline int cdiv(int a, int b) { return (a + b - 1) / b; }

extern "C" void kernel_launch(void* const* d_in, const int* in_sizes, int n_in,
                              void* d_out, int out_size)
{
    const float* x      = (const float*)d_in[0];
    const float* W_emb  = (const float*)d_in[1];
    const float* b_emb  = (const float*)d_in[2];
    const float* Wg1    = (const float*)d_in[3];
    const float* bg1    = (const float*)d_in[4];
    const float* Wg2    = (const float*)d_in[5];
    const float* bg2    = (const float*)d_in[6];
    const float* Wg3    = (const float*)d_in[7];
    const float* bg3    = (const float*)d_in[8];
    const float* Wf1    = (const float*)d_in[9];
    const float* bf1    = (const float*)d_in[10];
    const float* Wf2    = (const float*)d_in[11];
    const float* bf2    = (const float*)d_in[12];
    const int*   labels = (const int*)d_in[13];
    float* out = (float*)d_out;

    float *P, *Q, *rel, *fo;
    float *Wf2p, *b1p, *b2p, *b3p, *bf1p;
    uint32_t *xSp, *taggedSp, *H1Sp, *H2Sp, *WembSp, *W1tSp, *W1bSp, *W2Sp, *W3Sp, *Wf1Sp;
    cudaGetSymbolAddress((void**)&P, g_P);
    cudaGetSymbolAddress((void**)&Q, g_Q);
    cudaGetSymbolAddress((void**)&rel, g_rel);
    cudaGetSymbolAddress((void**)&fo, g_fo);
    cudaGetSymbolAddress((void**)&xSp, g_xSp);
    cudaGetSymbolAddress((void**)&taggedSp, g_taggedSp);
    cudaGetSymbolAddress((void**)&H1Sp, g_H1Sp);
    cudaGetSymbolAddress((void**)&H2Sp, g_H2Sp);
    cudaGetSymbolAddress((void**)&WembSp, g_WembSp);
    cudaGetSymbolAddress((void**)&W1tSp, g_W1tSp);
    cudaGetSymbolAddress((void**)&W1bSp, g_W1bSp);
    cudaGetSymbolAddress((void**)&W2Sp, g_W2Sp);
    cudaGetSymbolAddress((void**)&W3Sp, g_W3Sp);
    cudaGetSymbolAddress((void**)&Wf1Sp, g_Wf1Sp);
    cudaGetSymbolAddress((void**)&Wf2p, g_Wf2p);
    cudaGetSymbolAddress((void**)&b1p, g_b1);
    cudaGetSymbolAddress((void**)&b2p, g_b2);
    cudaGetSymbolAddress((void**)&b3p, g_b3);
    cudaGetSymbolAddress((void**)&bf1p, g_bf1);

    const int SMB2 = 2 * STG * 4;   // 33024 bytes (reg pipeline)
    const int SMB3 = 3 * STG * 4;   // 49536 bytes (cp.async pipeline)
    cudaFuncSetAttribute(mmagemm_k<1,2,1,0>, cudaFuncAttributeMaxDynamicSharedMemorySize, SMB3);
    cudaFuncSetAttribute(pqgemm_k,           cudaFuncAttributeMaxDynamicSharedMemorySize, SMB3);
    cudaFuncSetAttribute(mmagemm_k<2,2,1,1>, cudaFuncAttributeMaxDynamicSharedMemorySize, SMB3);
    cudaFuncSetAttribute(mmagemm_k<5,2,0,1>, cudaFuncAttributeMaxDynamicSharedMemorySize, SMB3);
    cudaFuncSetAttribute(mmagemm_k<4,0,0,1>, cudaFuncAttributeMaxDynamicSharedMemorySize, SMB2);

    // ---- one-time prep: all weight splits + tags + bias pads (1 launch) ----
    const int PREP_TOTAL = 4*400*1024 + 2*9*33*1024 + 3*9*66*1024 + 64*1024 + 5*TP;
    prep_k<<<cdiv(PREP_TOTAL, 256), 256>>>(
        WembSp, W1tSp, W1bSp, W2Sp, W3Sp, Wf1Sp, taggedSp,
        b1p, b2p, b3p, bf1p, Wf2p,
        W_emb, Wg1, Wg2, Wg3, Wf1, bg1, bg2, bg3, bf1, Wf2);
    // pre-split x into A-fragment layout
    xsplit_k<<<dim3(50, 64), 256>>>(xSp, x);
    cudaMemsetAsync(fo, 0, M_REL * sizeof(float));

    // emb = x @ W_emb + b_emb -> taggedSp (cp.async; kb 0..31 data, kb 32 tags)
    mmagemm_k<1,2,1,0><<<dim3(4, M_EMB / 128), 256, SMB3>>>(
        nullptr, 0, xSp, WembSp, 512, nullptr, 0, taggedSp, 33, KE, b_emb, nullptr);
    // P and Q in ONE launch (18 n-tiles: 0..8 -> P, 9..17 -> Q)
    pqgemm_k<<<dim3(18, M_EMB / 128), 256, SMB3>>>(taggedSp, W1tSp, W1bSp, P, Q);
    // H1 = relu(P[j]+Q[k]+b1), split once into H1Sp
    expandsp_k<<<dim3(66, NBATCH), 256>>>(P, Q, b1p, H1Sp);
    // L2: H2 = relu(H1 @ Wg2 + b2) -> H2Sp (split layout)
    mmagemm_k<2,2,1,1><<<dim3(9, M_PAIR / 128), 256, SMB3>>>(
        nullptr, 0, H1Sp, W2Sp, TP, nullptr, 0, H2Sp, 66, TP, b2p, nullptr);
    // L3: relations fused — 8-row sums + cross-k combine -> rel
    mmagemm_k<5,2,0,1><<<dim3(9, M_PAIR / 128), 256, SMB3>>>(
        nullptr, 0, H2Sp, W3Sp, TP, rel, TP, nullptr, 0, TP, b3p, nullptr);
    // f: Hf = relu(rel @ Wf1 + bf1); f_out partial-dot fused via atomics -> fo
    mmagemm_k<4,0,0,1><<<dim3(9, M_REL / 128), 256, SMB2>>>(
        rel, TP, nullptr, Wf1Sp, TP, fo, TP, nullptr, 0, TP, bf1p, Wf2p);
    loss_k<<<1, 512>>>(fo, labels, bf2, out);
}

// round 16
// speedup vs baseline: 1.3347x; 1.0072x over previous
#include <cuda_runtime.h>
#include <cuda_bf16.h>
#include <cstdint>
#include <math.h>

#define NBATCH  512
#define T       1042
#define TP      1056
#define KE      6400
#define KT      528
#define M_EMB   8192
#define M_PAIR  65536
#define M_REL   4096

// ---------------- scratch (device globals; no allocation) ----------------
__device__ __align__(16) float g_P[(size_t)M_EMB * TP];
__device__ __align__(16) float g_Q[(size_t)M_EMB * TP];
__device__ __align__(16) float g_fo[M_REL];
// split (bf16 hi/lo, fragment-permuted) buffers: [tile][kb][limb][1024] u32
__device__ __align__(16) uint32_t g_xSp[(size_t)64 * 400 * 2048];
__device__ __align__(16) uint32_t g_taggedSp[(size_t)64 * 33 * 2048];
__device__ __align__(16) uint32_t g_H1Sp[(size_t)512 * 66 * 2048];
__device__ __align__(16) uint32_t g_H2Sp[(size_t)512 * 66 * 2048];
__device__ __align__(16) uint32_t g_relSp[(size_t)32 * 66 * 2048];
__device__ __align__(16) uint32_t g_WembSp[(size_t)4 * 400 * 2048];
__device__ __align__(16) uint32_t g_W1tSp[(size_t)9 * 33 * 2048];
__device__ __align__(16) uint32_t g_W1bSp[(size_t)9 * 33 * 2048];
__device__ __align__(16) uint32_t g_W2Sp[(size_t)9 * 66 * 2048];
__device__ __align__(16) uint32_t g_W3Sp[(size_t)9 * 66 * 2048];
__device__ __align__(16) uint32_t g_Wf1Sp[(size_t)9 * 66 * 2048];
__device__ __align__(16) float g_Wf2p[TP];
__device__ __align__(16) float g_b1[TP];
__device__ __align__(16) float g_b2[TP];
__device__ __align__(16) float g_b3[TP];
__device__ __align__(16) float g_bf1[TP];

// ---------------- helpers -------------------------------------------------
__device__ __forceinline__ void split2(float a, float b, uint32_t& h, uint32_t& l) {
    __nv_bfloat16 ha = __float2bfloat16(a);
    __nv_bfloat16 hb = __float2bfloat16(b);
    float fa = __bfloat162float(ha), fb = __bfloat162float(hb);
    __nv_bfloat16 la = __float2bfloat16(a - fa);
    __nv_bfloat16 lb = __float2bfloat16(b - fb);
    h = (uint32_t)__bfloat16_as_ushort(ha) | ((uint32_t)__bfloat16_as_ushort(hb) << 16);
    l = (uint32_t)__bfloat16_as_ushort(la) | ((uint32_t)__bfloat16_as_ushort(lb) << 16);
}

__device__ __forceinline__ void mma16(float acc[4], const uint32_t a[4], const uint32_t b[2]) {
    asm volatile(
        "mma.sync.aligned.m16n8k16.row.col.f32.bf16.bf16.f32 "
        "{%0,%1,%2,%3},{%4,%5,%6,%7},{%8,%9},{%0,%1,%2,%3};"
        : "+f"(acc[0]), "+f"(acc[1]), "+f"(acc[2]), "+f"(acc[3])
        : "r"(a[0]), "r"(a[1]), "r"(a[2]), "r"(a[3]), "r"(b[0]), "r"(b[1]));
}

__device__ __forceinline__ uint32_t smem_u32(const void* p) {
    uint32_t a;
    asm("{ .reg .u64 t; cvta.to.shared.u64 t, %1; cvt.u32.u64 %0, t; }" : "=r"(a) : "l"(p));
    return a;
}
#define CP16(saddr, gptr) \
    asm volatile("cp.async.cg.shared.global [%0], [%1], 16;" :: "r"(saddr), "l"(gptr))
#define CP4(saddr, gptr) \
    asm volatile("cp.async.ca.shared.global [%0], [%1], 4;" :: "r"(saddr), "l"(gptr))
#define CP_COMMIT() asm volatile("cp.async.commit_group;" ::: "memory")
#define CP_WAIT1()  asm volatile("cp.async.wait_group 1;" ::: "memory")
#define CP_WAIT0()  asm volatile("cp.async.wait_group 0;" ::: "memory")

constexpr int A_HI = 0;
constexpr int A_LO = 1032;
constexpr int B_HI = 2064;
constexpr int B_LO = 3096;
constexpr int STG  = 4128;          // u32 per stage

// split-fragment scalar store: value pair (kg, kg+1) of row rl within m-tile mt
__device__ __forceinline__ void store_split(
    uint32_t* Csp, int KBC, int mt, int rl, int kg, float v0, float v1)
{
    uint32_t h, l;
    split2(v0, v1, h, l);
    int kb = kg >> 4, kk = kg & 15;
    int idx = (rl >> 4) * 128 + ((rl & 7) * 4 + ((kk & 7) >> 1)) * 4
            + ((rl >> 3) & 1) + 2 * (kk >> 3);
    size_t base = ((size_t)mt * KBC + kb) * 2048 + idx;
    Csp[base] = h;
    Csp[base + 1024] = l;
}

// ---------------- shared epilogue -----------------------------------------
// EPI: 0 plain store, 1 +bias, 2 +bias+relu  (AOUT selects f32 vs split)
//      4 bias+relu+dot(Wf2) -> atomicAdd fo   (C = fo)
//      5 bias+relu+8row-sum+relations -> relSp (split layout, Csp)
template<int EPI, int AOUT, int NF>
__device__ __forceinline__ void epilogue(
    int bx, float (&acc)[4][NF][4], int Ncols, float* C, int ldc,
    uint32_t* Csp, int KBC, const float* bias, const float* w2v,
    float* smf)
{
    const int t = threadIdx.x;
    const int m0 = blockIdx.y * 128, n0 = bx * 128;
    const int L = t & 31, wid = t >> 5, wm = wid >> 2, wn = wid & 3;
    const int baseRow = m0 + wm * 64;

    if (EPI == 4) {
        float pr[4][2];
        #pragma unroll
        for (int mf = 0; mf < 4; mf++) { pr[mf][0] = 0.f; pr[mf][1] = 0.f; }
        #pragma unroll
        for (int mf = 0; mf < 4; mf++) {
            #pragma unroll
            for (int nf = 0; nf < NF; nf++) {
                int col = n0 + wn * 8 * NF + nf * 8 + (L & 3) * 2;
                float2 b2 = *(const float2*)(bias + col);
                float c0 = fmaxf(acc[mf][nf][0] + b2.x, 0.f);
                float c1 = fmaxf(acc[mf][nf][1] + b2.y, 0.f);
                float c2 = fmaxf(acc[mf][nf][2] + b2.x, 0.f);
                float c3 = fmaxf(acc[mf][nf][3] + b2.y, 0.f);
                float2 w = *(const float2*)(w2v + col);
                pr[mf][0] += c0 * w.x + c1 * w.y;
                pr[mf][1] += c2 * w.x + c3 * w.y;
            }
        }
        #pragma unroll
        for (int mf = 0; mf < 4; mf++) {
            pr[mf][0] += __shfl_xor_sync(0xffffffffu, pr[mf][0], 1);
            pr[mf][0] += __shfl_xor_sync(0xffffffffu, pr[mf][0], 2);
            pr[mf][1] += __shfl_xor_sync(0xffffffffu, pr[mf][1], 1);
            pr[mf][1] += __shfl_xor_sync(0xffffffffu, pr[mf][1], 2);
            if ((L & 3) == 0) {
                int row = baseRow + mf * 16 + (L >> 2);
                atomicAdd(C + row, pr[mf][0]);
                atomicAdd(C + row + 8, pr[mf][1]);
            }
        }
        return;
    }

    if (EPI == 5) {
        const int NFC = NF * 32;
        __syncthreads();                    // stages fully consumed before smem reuse
        #pragma unroll
        for (int mf = 0; mf < 4; mf++) {
            #pragma unroll
            for (int nf = 0; nf < NF; nf++) {
                int colL = wn * 8 * NF + nf * 8 + (L & 3) * 2;
                float2 b2 = *(const float2*)(bias + n0 + colL);
                float c0 = fmaxf(acc[mf][nf][0] + b2.x, 0.f);
                float c1 = fmaxf(acc[mf][nf][1] + b2.y, 0.f);
                float c2 = fmaxf(acc[mf][nf][2] + b2.x, 0.f);
                float c3 = fmaxf(acc[mf][nf][3] + b2.y, 0.f);
                c0 += __shfl_down_sync(0xffffffffu, c0, 16);
                c0 += __shfl_down_sync(0xffffffffu, c0, 8);
                c0 += __shfl_down_sync(0xffffffffu, c0, 4);
                c1 += __shfl_down_sync(0xffffffffu, c1, 16);
                c1 += __shfl_down_sync(0xffffffffu, c1, 8);
                c1 += __shfl_down_sync(0xffffffffu, c1, 4);
                c2 += __shfl_down_sync(0xffffffffu, c2, 16);
                c2 += __shfl_down_sync(0xffffffffu, c2, 8);
                c2 += __shfl_down_sync(0xffffffffu, c2, 4);
                c3 += __shfl_down_sync(0xffffffffu, c3, 16);
                c3 += __shfl_down_sync(0xffffffffu, c3, 8);
                c3 += __shfl_down_sync(0xffffffffu, c3, 4);
                if (L < 4) {
                    int gl = (wm * 64 + mf * 16) >> 3;      // 0,2,4,...,14
                    smf[gl * NFC + colL]           = c0;
                    smf[gl * NFC + colL + 1]       = c1;
                    smf[(gl + 1) * NFC + colL]     = c2;
                    smf[(gl + 1) * NFC + colL + 1] = c3;
                }
            }
        }
        __syncthreads();
        const int b = blockIdx.y;
        const int mt = b >> 4;
        if (NF == 4) {
            int p = t & 63, a2 = t >> 6;            // 64 col-pairs, a2 0..3
            float cs0 = 0.f, cs1 = 0.f;
            #pragma unroll
            for (int k = 0; k < 8; k++) {
                cs0 += smf[k * 128 + 2 * p];
                cs1 += smf[k * 128 + 2 * p + 1];
            }
            #pragma unroll
            for (int ai = 0; ai < 2; ai++) {
                int a = a2 * 2 + ai;
                float v0 = cs0 + smf[(8 + a) * 128 + 2 * p];
                float v1 = cs1 + smf[(8 + a) * 128 + 2 * p + 1];
                store_split(Csp, 66, mt, (b & 15) * 8 + a, n0 + 2 * p, v0, v1);
            }
        } else {
            if (t < 128) {
                int p = t & 15, a = t >> 4;         // 16 col-pairs, a 0..7
                float cs0 = 0.f, cs1 = 0.f;
                #pragma unroll
                for (int k = 0; k < 8; k++) {
                    cs0 += smf[k * 32 + 2 * p];
                    cs1 += smf[k * 32 + 2 * p + 1];
                }
                float v0 = cs0 + smf[(8 + a) * 32 + 2 * p];
                float v1 = cs1 + smf[(8 + a) * 32 + 2 * p + 1];
                store_split(Csp, 66, mt, (b & 15) * 8 + a, n0 + 2 * p, v0, v1);
            }
        }
        return;
    }

    if (AOUT == 1) {
        const int mt = blockIdx.y;
        if (NF == 4) {
            #pragma unroll
            for (int mf = 0; mf < 4; mf++) {
                #pragma unroll
                for (int f = 0; f < 2; f++) {
                    int kbC = (n0 >> 4) + wn * 2 + f;
                    if (kbC < KBC) {
                        uint32_t hi[4], lo[4];
                        #pragma unroll
                        for (int s = 0; s < 2; s++) {
                            int nf = 2 * f + s;
                            int col = n0 + wn * 32 + nf * 8 + (L & 3) * 2;
                            float c0 = acc[mf][nf][0], c1 = acc[mf][nf][1];
                            float c2 = acc[mf][nf][2], c3 = acc[mf][nf][3];
                            if (EPI >= 1) {
                                float2 b2 = *(const float2*)(bias + col);
                                c0 += b2.x; c1 += b2.y; c2 += b2.x; c3 += b2.y;
                            }
                            if (EPI >= 2) {
                                c0 = fmaxf(c0, 0.f); c1 = fmaxf(c1, 0.f);
                                c2 = fmaxf(c2, 0.f); c3 = fmaxf(c3, 0.f);
                            }
                            split2(c0, c1, hi[2 * s], lo[2 * s]);
                            split2(c2, c3, hi[2 * s + 1], lo[2 * s + 1]);
                        }
                        size_t base = ((size_t)mt * KBC + kbC) * 2048 + (wm * 4 + mf) * 128 + L * 4;
                        *(uint4*)(Csp + base)        = make_uint4(hi[0], hi[1], hi[2], hi[3]);
                        *(uint4*)(Csp + base + 1024) = make_uint4(lo[0], lo[1], lo[2], lo[3]);
                    }
                }
            }
        } else {
            #pragma unroll
            for (int mf = 0; mf < 4; mf++) {
                int col = n0 + wn * 8 + (L & 3) * 2;
                float c0 = acc[mf][0][0], c1 = acc[mf][0][1];
                float c2 = acc[mf][0][2], c3 = acc[mf][0][3];
                if (EPI >= 1) {
                    float2 b2 = *(const float2*)(bias + col);
                    c0 += b2.x; c1 += b2.y; c2 += b2.x; c3 += b2.y;
                }
                if (EPI >= 2) {
                    c0 = fmaxf(c0, 0.f); c1 = fmaxf(c1, 0.f);
                    c2 = fmaxf(c2, 0.f); c3 = fmaxf(c3, 0.f);
                }
                uint32_t h0, l0, h1, l1;
                split2(c0, c1, h0, l0);
                split2(c2, c3, h1, l1);
                int kbC = (n0 >> 4) + (wn >> 1);
                size_t base = ((size_t)mt * KBC + kbC) * 2048 + (wm * 4 + mf) * 128
                            + L * 4 + 2 * (wn & 1);
                *(uint2*)(Csp + base)        = make_uint2(h0, h1);
                *(uint2*)(Csp + base + 1024) = make_uint2(l0, l1);
            }
        }
        return;
    }

    #pragma unroll
    for (int mf = 0; mf < 4; mf++) {
        #pragma unroll
        for (int nf = 0; nf < NF; nf++) {
            int col = n0 + wn * 8 * NF + nf * 8 + (L & 3) * 2;
            bool cv = col < Ncols;
            float c0 = acc[mf][nf][0], c1 = acc[mf][nf][1];
            float c2 = acc[mf][nf][2], c3 = acc[mf][nf][3];
            if (EPI >= 1) {
                float2 b2 = cv ? *(const float2*)(bias + col) : make_float2(0.f, 0.f);
                c0 += b2.x; c1 += b2.y; c2 += b2.x; c3 += b2.y;
            }
            if (EPI >= 2) {
                c0 = fmaxf(c0, 0.f); c1 = fmaxf(c1, 0.f);
                c2 = fmaxf(c2, 0.f); c3 = fmaxf(c3, 0.f);
            }
            if (cv) {
                int row = baseRow + mf * 16 + (L >> 2);
                *(float2*)(C + (size_t)row * ldc + col)       = make_float2(c0, c1);
                *(float2*)(C + (size_t)(row + 8) * ldc + col) = make_float2(c2, c3);
            }
        }
    }
}

// ---------------- consume one stage ---------------------------------------
template<int NF>
__device__ __forceinline__ void consume_stage(
    const uint32_t* stg, float (&acc)[4][NF][4], int L, int wm, int wn)
{
    uint32_t ah[4][4], al[4][4], bh[NF][2], bl[NF][2];
    #pragma unroll
    for (int mf = 0; mf < 4; mf++) {
        const uint32_t* ab = stg + (wm * 4 + mf) * 128 + L * 4;
        *(uint4*)ah[mf] = *(const uint4*)(ab + A_HI);
        *(uint4*)al[mf] = *(const uint4*)(ab + A_LO);
    }
    #pragma unroll
    for (int nf = 0; nf < NF; nf++) {
        const uint32_t* bb = stg + (wn * NF + nf) * 64 + L * 2;
        *(uint2*)bh[nf] = *(const uint2*)(bb + B_HI);
        *(uint2*)bl[nf] = *(const uint2*)(bb + B_LO);
    }
    #pragma unroll
    for (int mf = 0; mf < 4; mf++)
        #pragma unroll
        for (int nf = 0; nf < NF; nf++) {
            mma16(acc[mf][nf], ah[mf], bh[nf]);
            mma16(acc[mf][nf], ah[mf], bl[nf]);
            mma16(acc[mf][nf], al[mf], bh[nf]);
        }
}

// ---------------- reg-pipeline body (A = f32, split on the fly) -----------
template<int EPI, int AOUT, int NF>
__device__ __forceinline__ void gemm_reg(
    int bx, const float* __restrict__ A, int lda,
    const uint32_t* __restrict__ Bsp,
    int Ncols, float* __restrict__ C, int ldc,
    uint32_t* __restrict__ Csp, int KBC,
    int K, const float* __restrict__ bias, const float* __restrict__ w2v,
    uint32_t* smu)
{
    const int t  = threadIdx.x;
    const int m0 = blockIdx.y * 128;
    const int KB = K >> 4;
    const int prow = t >> 1, pks = t & 1;
    const int p8 = prow & 7, rb8 = (prow >> 3) & 1, fb = prow >> 4;
    const float* ApA = A + (size_t)(m0 + prow) * lda + pks * 8;

    float va[8];
    uint4 hB, lB;
    const int L = t & 31, wid = t >> 5, wm = wid >> 2, wn = wid & 3;
    float acc[4][NF][4];
    #pragma unroll
    for (int i = 0; i < 4; i++)
        #pragma unroll
        for (int j = 0; j < NF; j++)
            #pragma unroll
            for (int v = 0; v < 4; v++) acc[i][j][v] = 0.f;

    auto ldtile = [&](int kb) {
        const uint32_t* gB = Bsp + ((size_t)(bx * KB + kb)) * 2048;
        if (NF == 4) {
            hB = ((const uint4*)gB)[t];
            lB = ((const uint4*)gB)[256 + t];
        } else {
            hB.x = gB[t];
            lB.x = gB[1024 + t];
        }
        int k0 = kb * 16;
        float4 x0 = *(const float4*)(ApA + k0);
        float4 x1 = *(const float4*)(ApA + k0 + 4);
        va[0] = x0.x; va[1] = x0.y; va[2] = x0.z; va[3] = x0.w;
        va[4] = x1.x; va[5] = x1.y; va[6] = x1.z; va[7] = x1.w;
    };
    auto sttile = [&](uint32_t* stg) {
        if (NF == 4) {
            *(uint4*)(stg + B_HI + t * 4) = hB;
            *(uint4*)(stg + B_LO + t * 4) = lB;
        } else {
            stg[B_HI + t] = hB.x;
            stg[B_LO + t] = lB.x;
        }
        #pragma unroll
        for (int j = 0; j < 4; j++) {
            uint32_t h, l;
            split2(va[2 * j], va[2 * j + 1], h, l);
            int ai = fb * 128 + (p8 * 4 + j) * 4 + rb8 + 2 * pks;
            stg[A_HI + ai] = h;
            stg[A_LO + ai] = l;
        }
    };

    ldtile(0);
    sttile(smu);
    __syncthreads();
    for (int kb = 0; kb < KB; kb++) {
        if (kb + 1 < KB) ldtile(kb + 1);
        consume_stage<NF>(smu + (kb & 1) * STG, acc, L, wm, wn);
        if (kb + 1 < KB) sttile(smu + ((kb + 1) & 1) * STG);
        __syncthreads();
    }
    epilogue<EPI, AOUT, NF>(bx, acc, Ncols, C, ldc, Csp, KBC, bias, w2v, (float*)smu);
}

// ---------------- cp.async 3-stage body (A pre-split, pure copy) ----------
template<int EPI, int AOUT, int NF>
__device__ __forceinline__ void gemm_cpa(
    int bx, const uint32_t* __restrict__ Asp,
    const uint32_t* __restrict__ Bsp,
    int Ncols, float* __restrict__ C, int ldc,
    uint32_t* __restrict__ Csp, int KBC,
    int K, const float* __restrict__ bias, const float* __restrict__ w2v,
    uint32_t* smu)
{
    const int t  = threadIdx.x;
    const int KB = K >> 4;
    const int L = t & 31, wid = t >> 5, wm = wid >> 2, wn = wid & 3;
    const uint32_t sbase = smem_u32(smu);

    float acc[4][NF][4];
    #pragma unroll
    for (int i = 0; i < 4; i++)
        #pragma unroll
        for (int j = 0; j < NF; j++)
            #pragma unroll
            for (int v = 0; v < 4; v++) acc[i][j][v] = 0.f;

    auto copyasync = [&](int kb, int stage) {
        uint32_t s0 = sbase + (uint32_t)stage * STG * 4;
        const uint32_t* gA = Asp + ((size_t)(blockIdx.y * KB + kb)) * 2048;
        const uint32_t* gB = Bsp + ((size_t)(bx * KB + kb)) * 2048;
        CP16(s0 + (A_HI + t * 4) * 4, gA + t * 4);
        CP16(s0 + (A_LO + t * 4) * 4, gA + 1024 + t * 4);
        if (NF == 4) {
            CP16(s0 + (B_HI + t * 4) * 4, gB + t * 4);
            CP16(s0 + (B_LO + t * 4) * 4, gB + 1024 + t * 4);
        } else {
            CP4(s0 + (B_HI + t) * 4, gB + t);
            CP4(s0 + (B_LO + t) * 4, gB + 1024 + t);
        }
        CP_COMMIT();
    };

    copyasync(0, 0);
    copyasync(1, 1);
    int stage = 0;
    for (int kb = 0; kb < KB; kb++) {
        if (kb < KB - 1) CP_WAIT1(); else CP_WAIT0();
        __syncthreads();
        consume_stage<NF>(smu + stage * STG, acc, L, wm, wn);
        if (kb + 2 < KB) {
            int ns = stage + 2;
            if (ns >= 3) ns -= 3;
            copyasync(kb + 2, ns);
        }
        stage = (stage + 1 == 3) ? 0 : stage + 1;
    }
    epilogue<EPI, AOUT, NF>(bx, acc, Ncols, C, ldc, Csp, KBC, bias, w2v, (float*)smu);
}

// ---------------- kernels -------------------------------------------------
template<int EPI, int ASRC, int AOUT, int NARROW>
__global__ void __launch_bounds__(256, 1) mmagemm_k(
    const float* __restrict__ A, int lda,
    const uint32_t* __restrict__ Asp,
    const uint32_t* __restrict__ Bsp,
    int Ncols, float* __restrict__ C, int ldc,
    uint32_t* __restrict__ Csp, int KBC,
    int K, const float* __restrict__ bias, const float* __restrict__ w2v)
{
    extern __shared__ uint32_t smu[];
    const int bx = blockIdx.x;
    if (ASRC == 2) {
        if (NARROW && bx == gridDim.x - 1)
            gemm_cpa<EPI, AOUT, 1>(bx, Asp, Bsp, Ncols, C, ldc, Csp, KBC, K, bias, w2v, smu);
        else
            gemm_cpa<EPI, AOUT, 4>(bx, Asp, Bsp, Ncols, C, ldc, Csp, KBC, K, bias, w2v, smu);
    } else {
        if (NARROW && bx == gridDim.x - 1)
            gemm_reg<EPI, AOUT, 1>(bx, A, lda, Bsp, Ncols, C, ldc, Csp, KBC, K, bias, w2v, smu);
        else
            gemm_reg<EPI, AOUT, 4>(bx, A, lda, Bsp, Ncols, C, ldc, Csp, KBC, K, bias, w2v, smu);
    }
}

// P and Q GEMMs merged in one launch: grid (18, 64).
__global__ void __launch_bounds__(256, 1) pqgemm_k(
    const uint32_t* __restrict__ Asp,
    const uint32_t* __restrict__ W1t, const uint32_t* __restrict__ W1b,
    float* __restrict__ P, float* __restrict__ Q)
{
    extern __shared__ uint32_t smu[];
    const bool isQ = blockIdx.x >= 9;
    const int bx = isQ ? blockIdx.x - 9 : blockIdx.x;
    const uint32_t* Bsp = isQ ? W1b : W1t;
    float* C = isQ ? Q : P;
    if (bx == 8)
        gemm_cpa<0, 0, 1>(bx, Asp, Bsp, TP, C, TP, nullptr, 0, KT, nullptr, nullptr, smu);
    else
        gemm_cpa<0, 0, 4>(bx, Asp, Bsp, TP, C, TP, nullptr, 0, KT, nullptr, nullptr, smu);
}

// ---------------- x pre-split: f32 -> A-fragment split layout -------------
__global__ void xsplit_k(uint32_t* __restrict__ dst, const float* __restrict__ src)
{
    const int mt = blockIdx.y;
    const int t = threadIdx.x;
    const int prow = t >> 1, pks = t & 1;
    const int p8 = prow & 7, rb8 = (prow >> 3) & 1, fb = prow >> 4;
    const float* A = src + (size_t)(mt * 128 + prow) * KE + pks * 8;
    const int kb0 = blockIdx.x * 8;
    #pragma unroll 2
    for (int kb = kb0; kb < kb0 + 8; kb++) {
        float4 x0 = *(const float4*)(A + kb * 16);
        float4 x1 = *(const float4*)(A + kb * 16 + 4);
        float va[8] = {x0.x, x0.y, x0.z, x0.w, x1.x, x1.y, x1.z, x1.w};
        uint32_t* stg = dst + ((size_t)mt * 400 + kb) * 2048;
        #pragma unroll
        for (int j = 0; j < 4; j++) {
            uint32_t h, l;
            split2(va[2 * j], va[2 * j + 1], h, l);
            int ai = fb * 128 + (p8 * 4 + j) * 4 + rb8 + 2 * pks;
            stg[ai] = h;
            stg[1024 + ai] = l;
        }
    }
}

// ---------------- merged prep: all weight splits + tags + bias pads -------
__device__ __forceinline__ void wsplit_body(
    uint32_t* dst, const float* src, int idx,
    int KB, int sK, int sN, int sStride, int rowOff)
{
    int bi  = idx & 1023;
    int pks = bi & 1;
    int lj  = (bi >> 1) & 31;
    int nb  = bi >> 6;
    int p8  = lj >> 2, j = lj & 3;
    int tile = idx >> 10;
    int nt = tile / KB, kb = tile % KB;
    int n = nt * 128 + nb * 8 + p8;
    int k = kb * 16 + pks * 8 + 2 * j;
    float w0 = (k < sK && n < sN)     ? src[(size_t)(k + rowOff) * sStride + n]     : 0.f;
    float w1 = (k + 1 < sK && n < sN) ? src[(size_t)(k + 1 + rowOff) * sStride + n] : 0.f;
    uint32_t h, l;
    split2(w0, w1, h, l);
    dst[(size_t)tile * 2048 + bi] = h;
    dst[(size_t)tile * 2048 + 1024 + bi] = l;
}

__global__ void prep_k(
    uint32_t* __restrict__ WembSp, uint32_t* __restrict__ W1tSp,
    uint32_t* __restrict__ W1bSp, uint32_t* __restrict__ W2Sp,
    uint32_t* __restrict__ W3Sp, uint32_t* __restrict__ Wf1Sp,
    uint32_t* __restrict__ tsp,
    float* __restrict__ b1p, float* __restrict__ b2p, float* __restrict__ b3p,
    float* __restrict__ bf1p, float* __restrict__ Wf2p,
    const float* __restrict__ W_emb, const float* __restrict__ Wg1,
    const float* __restrict__ Wg2, const float* __restrict__ Wg3,
    const float* __restrict__ Wf1, const float* __restrict__ bg1,
    const float* __restrict__ bg2, const float* __restrict__ bg3,
    const float* __restrict__ bf1, const float* __restrict__ Wf2)
{
    int idx = blockIdx.x * blockDim.x + threadIdx.x;
    const int C0 = 4 * 400 * 1024;
    const int C1 = 9 * 33 * 1024;
    const int C3 = 9 * 66 * 1024;
    const int C6 = 64 * 1024;

    if (idx < C0) { wsplit_body(WembSp, W_emb, idx, 400, KE, 512, 512, 0); return; }
    idx -= C0;
    if (idx < C1) { wsplit_body(W1tSp, Wg1, idx, 33, 521, T, T, 0); return; }
    idx -= C1;
    if (idx < C1) { wsplit_body(W1bSp, Wg1, idx, 33, 521, T, T, 521); return; }
    idx -= C1;
    if (idx < C3) { wsplit_body(W2Sp, Wg2, idx, 66, T, T, T, 0); return; }
    idx -= C3;
    if (idx < C3) { wsplit_body(W3Sp, Wg3, idx, 66, T, T, T, 0); return; }
    idx -= C3;
    if (idx < C3) { wsplit_body(Wf1Sp, Wf1, idx, 66, T, T, T, 0); return; }
    idx -= C3;
    if (idx < C6) {
        int ai = idx & 1023;
        int mt = idx >> 10;
        int w = ai & 127, fbv = ai >> 7;
        int lane = w >> 2, rem = w & 3;
        int rb8 = rem & 1, pks = rem >> 1;
        int p8 = lane >> 2, j = lane & 3;
        int r = mt * 128 + fbv * 16 + rb8 * 8 + p8;
        int col = 512 + pks * 8 + 2 * j;
        int tpos = ((r & 15) < 8) ? (r & 15) : 8;
        int tcol = 512 + tpos;
        uint32_t h = 0;
        if (col == tcol)     h |= 0x3F80u;
        if (col + 1 == tcol) h |= 0x3F80u << 16;
        size_t base = ((size_t)mt * 33 + 32) * 2048 + ai;
        tsp[base] = h;
        tsp[base + 1024] = 0u;
        return;
    }
    idx -= C6;
    if (idx < 5 * TP) {
        int v = idx / TP, c = idx % TP;
        const float* s = (v == 0) ? bg1 : (v == 1) ? bg2 : (v == 2) ? bg3
                       : (v == 3) ? bf1 : Wf2;
        float* d = (v == 0) ? b1p : (v == 1) ? b2p : (v == 2) ? b3p
                 : (v == 3) ? bf1p : Wf2p;
        d[c] = (c < T) ? s[c] : 0.f;
    }
}

// ---- H1 expand + split: relu(P[b,j]+Q[b,k]+b1) -> H1Sp -------------------
__global__ void expandsp_k(const float* __restrict__ P, const float* __restrict__ Q,
                           const float* __restrict__ b1, uint32_t* __restrict__ H1sp)
{
    __shared__ float sP[8][16], sQ[16][16], sB[16];
    int b = blockIdx.y, kb = blockIdx.x;
    int t = threadIdx.x;
    int k0 = kb * 16;
    if (t < 96) {
        int row = t >> 2, q = t & 3;
        const float* src = (row < 8) ? (P + (size_t)(b * 16 + row) * TP)
                                     : (Q + (size_t)(b * 16 + row - 8) * TP);
        float4 v = *(const float4*)(src + k0 + q * 4);
        if (row < 8) *(float4*)&sP[row][q * 4] = v;
        else         *(float4*)&sQ[row - 8][q * 4] = v;
    } else if (t < 100) {
        int q = t - 96;
        *(float4*)&sB[q * 4] = *(const float4*)(b1 + k0 + q * 4);
    }
    __syncthreads();
    int L = t & 31;
    int p8 = L >> 2, j = L & 3;
    int fbv = t >> 5;
    uint32_t hi[4], lo[4];
    #pragma unroll
    for (int s = 0; s < 2; s++) {
        int kA = s * 8 + 2 * j;
        #pragma unroll
        for (int rb = 0; rb < 2; rb++) {
            int r = fbv * 16 + rb * 8 + p8;
            int jj = r & 7, kk = r >> 3;
            float e0 = fmaxf(sP[jj][kA]     + sQ[kk][kA]     + sB[kA],     0.f);
            float e1 = fmaxf(sP[jj][kA + 1] + sQ[kk][kA + 1] + sB[kA + 1], 0.f);
            split2(e0, e1, hi[2 * s + rb], lo[2 * s + rb]);
        }
    }
    size_t base = ((size_t)b * 66 + kb) * 2048 + t * 4;
    *(uint4*)(H1sp + base)        = make_uint4(hi[0], hi[1], hi[2], hi[3]);
    *(uint4*)(H1sp + base + 1024) = make_uint4(lo[0], lo[1], lo[2], lo[3]);
}

// ======================= small kernels ====================================
__inline__ __device__ float warp_sum(float v)
{
    #pragma unroll
    for (int o = 16; o; o >>= 1) v += __shfl_down_sync(0xffffffffu, v, o);
    return v;
}

__global__ void loss_k(const float* __restrict__ fo, const int* __restrict__ labels,
                       const float* __restrict__ bf2, float* __restrict__ out)
{
    int b = threadIdx.x;
    int lab = labels[b];
    float bias2 = bf2[0];
    float lsum = 0.f;
    float best = -1e30f; int bi = 0;
    #pragma unroll
    for (int a = 0; a < 8; a++) {
        float f = fo[b * 8 + a] + bias2;
        float l = fmaxf(f, 0.f) - f * ((a == lab) ? 1.f : 0.f) + log1pf(expf(-fabsf(f)));
        lsum += l;
        if (f > best) { best = f; bi = a; }
    }
    float cor = (bi == lab) ? 1.f : 0.f;
    lsum = warp_sum(lsum);
    cor  = warp_sum(cor);
    __shared__ float sl[16], sc[16];
    int wid = threadIdx.x >> 5, lane = threadIdx.x & 31;
    if (lane == 0) { sl[wid] = lsum; sc[wid] = cor; }
    __syncthreads();
    if (wid == 0) {
        float a = (lane < 16) ? sl[lane] : 0.f;
        float c = (lane < 16) ? sc[lane] : 0.f;
        a = warp_sum(a);
        c = warp_sum(c);
        if (lane == 0) {
            out[0] = a / (float)(NBATCH * 8);
            out[1] = c / (float)NBATCH;
        }
    }
}

// ======================= host =============================================
static inline int cdiv(int a, int b) { return (a + b - 1) / b; }

extern "C" void kernel_launch(void* const* d_in, const int* in_sizes, int n_in,
                              void* d_out, int out_size)
{
    const float* x      = (const float*)d_in[0];
    const float* W_emb  = (const float*)d_in[1];
    const float* b_emb  = (const float*)d_in[2];
    const float* Wg1    = (const float*)d_in[3];
    const float* bg1    = (const float*)d_in[4];
    const float* Wg2    = (const float*)d_in[5];
    const float* bg2    = (const float*)d_in[6];
    const float* Wg3    = (const float*)d_in[7];
    const float* bg3    = (const float*)d_in[8];
    const float* Wf1    = (const float*)d_in[9];
    const float* bf1    = (const float*)d_in[10];
    const float* Wf2    = (const float*)d_in[11];
    const float* bf2    = (const float*)d_in[12];
    const int*   labels = (const int*)d_in[13];
    float* out = (float*)d_out;

    float *P, *Q, *fo;
    float *Wf2p, *b1p, *b2p, *b3p, *bf1p;
    uint32_t *xSp, *taggedSp, *H1Sp, *H2Sp, *relSp;
    uint32_t *WembSp, *W1tSp, *W1bSp, *W2Sp, *W3Sp, *Wf1Sp;
    cudaGetSymbolAddress((void**)&P, g_P);
    cudaGetSymbolAddress((void**)&Q, g_Q);
    cudaGetSymbolAddress((void**)&fo, g_fo);
    cudaGetSymbolAddress((void**)&xSp, g_xSp);
    cudaGetSymbolAddress((void**)&taggedSp, g_taggedSp);
    cudaGetSymbolAddress((void**)&H1Sp, g_H1Sp);
    cudaGetSymbolAddress((void**)&H2Sp, g_H2Sp);
    cudaGetSymbolAddress((void**)&relSp, g_relSp);
    cudaGetSymbolAddress((void**)&WembSp, g_WembSp);
    cudaGetSymbolAddress((void**)&W1tSp, g_W1tSp);
    cudaGetSymbolAddress((void**)&W1bSp, g_W1bSp);
    cudaGetSymbolAddress((void**)&W2Sp, g_W2Sp);
    cudaGetSymbolAddress((void**)&W3Sp, g_W3Sp);
    cudaGetSymbolAddress((void**)&Wf1Sp, g_Wf1Sp);
    cudaGetSymbolAddress((void**)&Wf2p, g_Wf2p);
    cudaGetSymbolAddress((void**)&b1p, g_b1);
    cudaGetSymbolAddress((void**)&b2p, g_b2);
    cudaGetSymbolAddress((void**)&b3p, g_b3);
    cudaGetSymbolAddress((void**)&bf1p, g_bf1);

    const int SMB3 = 3 * STG * 4;   // 49536 bytes (cp.async pipeline)
    cudaFuncSetAttribute(mmagemm_k<1,2,1,0>, cudaFuncAttributeMaxDynamicSharedMemorySize, SMB3);
    cudaFuncSetAttribute(pqgemm_k,           cudaFuncAttributeMaxDynamicSharedMemorySize, SMB3);
    cudaFuncSetAttribute(mmagemm_k<2,2,1,1>, cudaFuncAttributeMaxDynamicSharedMemorySize, SMB3);
    cudaFuncSetAttribute(mmagemm_k<5,2,0,1>, cudaFuncAttributeMaxDynamicSharedMemorySize, SMB3);
    cudaFuncSetAttribute(mmagemm_k<4,2,0,1>, cudaFuncAttributeMaxDynamicSharedMemorySize, SMB3);

    // ---- one-time prep: all weight splits + tags + bias pads (1 launch) ----
    const int PREP_TOTAL = 4*400*1024 + 2*9*33*1024 + 3*9*66*1024 + 64*1024 + 5*TP;
    prep_k<<<cdiv(PREP_TOTAL, 256), 256>>>(
        WembSp, W1tSp, W1bSp, W2Sp, W3Sp, Wf1Sp, taggedSp,
        b1p, b2p, b3p, bf1p, Wf2p,
        W_emb, Wg1, Wg2, Wg3, Wf1, bg1, bg2, bg3, bf1, Wf2);
    // pre-split x into A-fragment layout
    xsplit_k<<<dim3(50, 64), 256>>>(xSp, x);
    cudaMemsetAsync(fo, 0, M_REL * sizeof(float));

    // emb = x @ W_emb + b_emb -> taggedSp (cp.async; kb 0..31 data, kb 32 tags)
    mmagemm_k<1,2,1,0><<<dim3(4, M_EMB / 128), 256, SMB3>>>(
        nullptr, 0, xSp, WembSp, 512, nullptr, 0, taggedSp, 33, KE, b_emb, nullptr);
    // P and Q in ONE launch (18 n-tiles: 0..8 -> P, 9..17 -> Q)
    pqgemm_k<<<dim3(18, M_EMB / 128), 256, SMB3>>>(taggedSp, W1tSp, W1bSp, P, Q);
    // H1 = relu(P[j]+Q[k]+b1), split once into H1Sp
    expandsp_k<<<dim3(66, NBATCH), 256>>>(P, Q, b1p, H1Sp);
    // L2: H2 = relu(H1 @ Wg2 + b2) -> H2Sp (split layout)
    mmagemm_k<2,2,1,1><<<dim3(9, M_PAIR / 128), 256, SMB3>>>(
        nullptr, 0, H1Sp, W2Sp, TP, nullptr, 0, H2Sp, 66, TP, b2p, nullptr);
    // L3: relations fused — 8-row sums + cross-k combine -> relSp (split layout)
    mmagemm_k<5,2,0,1><<<dim3(9, M_PAIR / 128), 256, SMB3>>>(
        nullptr, 0, H2Sp, W3Sp, TP, nullptr, 0, relSp, 66, TP, b3p, nullptr);
    // f: Hf = relu(rel @ Wf1 + bf1); f_out partial-dot fused via atomics -> fo
    // (cp.async pure-copy path, rel pre-split in L3 epilogue)
    mmagemm_k<4,2,0,1><<<dim3(9, M_REL / 128), 256, SMB3>>>(
        nullptr, 0, relSp, Wf1Sp, TP, fo, TP, nullptr, 0, TP, bf1p, Wf2p);
    loss_k<<<1, 512>>>(fo, labels, bf2, out);
}